// round 2
// baseline (speedup 1.0000x reference)
#include <cuda_runtime.h>
#include <math.h>

#define DMODEL 1024
#define SEQ    2048
#define BATCH  4
#define NHEADS 16
#define HDIM   64
#define DFF    4096
#define NROWS  8192      // BATCH*SEQ
#define MODW   6144

// ---------------- scratch (static device arrays; no allocation) ----------------
__device__ float g_mod[BATCH * MODW];
__device__ float g_xn[(size_t)NROWS * DMODEL];
__device__ float g_qkv[(size_t)NROWS * 3 * DMODEL];
__device__ float g_attn[(size_t)NROWS * DMODEL];
__device__ float g_x2[(size_t)NROWS * DMODEL];
__device__ float g_h[(size_t)NROWS * DFF];

// ---------------- helpers ----------------
__device__ __forceinline__ float gelu_tanh(float x) {
    float x3 = x * x * x;
    float u = 0.7978845608028654f * (x + 0.044715f * x3);
    return 0.5f * x * (1.0f + tanhf(u));
}

__device__ __forceinline__ void blockReduce2(float& a, float& b) {
    #pragma unroll
    for (int off = 16; off; off >>= 1) {
        a += __shfl_xor_sync(0xffffffffu, a, off);
        b += __shfl_xor_sync(0xffffffffu, b, off);
    }
    __shared__ float sa[8], sb[8];
    int w = threadIdx.x >> 5, l = threadIdx.x & 31;
    if (l == 0) { sa[w] = a; sb[w] = b; }
    __syncthreads();
    if (w == 0) {
        a = (l < 8) ? sa[l] : 0.0f;
        b = (l < 8) ? sb[l] : 0.0f;
        #pragma unroll
        for (int off = 4; off; off >>= 1) {
            a += __shfl_xor_sync(0xffffffffu, a, off);
            b += __shfl_xor_sync(0xffffffffu, b, off);
        }
        if (l == 0) { sa[0] = a; sb[0] = b; }
    }
    __syncthreads();
    a = sa[0]; b = sb[0];
}

// ---------------- 1) mod = c @ ada_W + ada_b ----------------
__global__ void mod_kernel(const float* __restrict__ c, const float* __restrict__ W,
                           const float* __restrict__ bias) {
    __shared__ float cs[1024];
    int b = blockIdx.y;
    int col = blockIdx.x * 256 + threadIdx.x;
    for (int i = threadIdx.x; i < 1024; i += 256) cs[i] = c[b * 1024 + i];
    __syncthreads();
    float acc = 0.0f;
    #pragma unroll 4
    for (int k = 0; k < 1024; k++) acc += cs[k] * W[(size_t)k * MODW + col];
    g_mod[b * MODW + col] = acc + bias[col];
}

// ---------------- 2) layernorm + modulate: y = LN(x)*w*(1+sc) + sh ----------------
__global__ void ln_mod_kernel(const float* __restrict__ X, const float* __restrict__ w,
                              int shOff, int scOff, float* __restrict__ out) {
    int row = blockIdx.x;
    int b = row >> 11;
    const float4* xr = (const float4*)(X + (size_t)row * DMODEL);
    float4 v = xr[threadIdx.x];
    float s = v.x + v.y + v.z + v.w;
    float ss = v.x * v.x + v.y * v.y + v.z * v.z + v.w * v.w;
    blockReduce2(s, ss);
    float mu = s * (1.0f / 1024.0f);
    float var = ss * (1.0f / 1024.0f) - mu * mu;
    float r = rsqrtf(var + 1e-5f);
    int d = threadIdx.x * 4;
    const float* mb = g_mod + b * MODW;
    float4 o;
    o.x = (v.x - mu) * r * w[d + 0] * (1.0f + mb[scOff + d + 0]) + mb[shOff + d + 0];
    o.y = (v.y - mu) * r * w[d + 1] * (1.0f + mb[scOff + d + 1]) + mb[shOff + d + 1];
    o.z = (v.z - mu) * r * w[d + 2] * (1.0f + mb[scOff + d + 2]) + mb[shOff + d + 2];
    o.w = (v.w - mu) * r * w[d + 3] * (1.0f + mb[scOff + d + 3]) + mb[shOff + d + 3];
    ((float4*)(out + (size_t)row * DMODEL))[threadIdx.x] = o;
}

// ---------------- 3) generic tiled SGEMM with templated epilogue ----------------
// MODE 0: C = acc
// MODE 1: C = res + gate[b][col] * acc
// MODE 2: C = gelu(acc + bias[col])
// MODE 3: C = res + gate[b][col] * (acc + bias[col])
template<int MODE>
__global__ void __launch_bounds__(256)
sgemm_kernel(const float* __restrict__ A, const float* __restrict__ B, float* __restrict__ C,
             int M, int N, int K,
             const float* __restrict__ res, const float* __restrict__ bias,
             const float* __restrict__ gate) {
    __shared__ float As[8][128];
    __shared__ float Bs[8][128];
    int t = threadIdx.x;
    int rowBase = blockIdx.y * 128, colBase = blockIdx.x * 128;
    int trow = (t >> 4) * 8, tcol = (t & 15) * 8;
    int aRow = t >> 1, aK4 = (t & 1) * 4;
    int bRow = t >> 5, bCol4 = (t & 31) * 4;
    const float* Ag = A + (size_t)(rowBase + aRow) * K + aK4;
    const float* Bg = B + (size_t)bRow * N + colBase + bCol4;
    float acc[8][8];
    #pragma unroll
    for (int i = 0; i < 8; i++)
        #pragma unroll
        for (int j = 0; j < 8; j++) acc[i][j] = 0.0f;

    for (int kt = 0; kt < K; kt += 8) {
        float4 a = *(const float4*)(Ag + kt);
        float4 bv = *(const float4*)(Bg + (size_t)kt * N);
        As[aK4 + 0][aRow] = a.x;
        As[aK4 + 1][aRow] = a.y;
        As[aK4 + 2][aRow] = a.z;
        As[aK4 + 3][aRow] = a.w;
        *(float4*)&Bs[bRow][bCol4] = bv;
        __syncthreads();
        #pragma unroll
        for (int k = 0; k < 8; k++) {
            float ar[8], br[8];
            *(float4*)(ar)     = *(float4*)&As[k][trow];
            *(float4*)(ar + 4) = *(float4*)&As[k][trow + 4];
            *(float4*)(br)     = *(float4*)&Bs[k][tcol];
            *(float4*)(br + 4) = *(float4*)&Bs[k][tcol + 4];
            #pragma unroll
            for (int i = 0; i < 8; i++)
                #pragma unroll
                for (int j = 0; j < 8; j++) acc[i][j] += ar[i] * br[j];
        }
        __syncthreads();
    }

    #pragma unroll
    for (int i = 0; i < 8; i++) {
        int gr = rowBase + trow + i;
        int bb = gr >> 11;
        size_t off = (size_t)gr * N;
        #pragma unroll
        for (int j = 0; j < 8; j++) {
            int gc = colBase + tcol + j;
            float v = acc[i][j];
            if (MODE == 0) {
                C[off + gc] = v;
            } else if (MODE == 1) {
                C[off + gc] = res[off + gc] + gate[bb * MODW + gc] * v;
            } else if (MODE == 2) {
                C[off + gc] = gelu_tanh(v + bias[gc]);
            } else {
                float u = v + bias[gc];
                C[off + gc] = res[off + gc] + gate[bb * MODW + gc] * u;
            }
        }
    }
}

// ---------------- 4) per-head rmsnorm + rope on q,k (in place in g_qkv) ----------------
__global__ void __launch_bounds__(1024)
rope_kernel(const float* __restrict__ qw, const float* __restrict__ kw,
            const float* __restrict__ cosb, const float* __restrict__ sinb) {
    __shared__ float sm[1024];
    __shared__ float part[32];
    int row = blockIdx.x;            // b*SEQ + s
    int s = row & (SEQ - 1);
    int t = threadIdx.x;             // 1024 threads
    int h = t >> 6, hd = t & 63;
    int wrp = t >> 5, lane = t & 31;
    float cs = cosb[s * HDIM + hd], sn = sinb[s * HDIM + hd];
    #pragma unroll
    for (int which = 0; which < 2; which++) {
        size_t base = ((size_t)row * 3 + which) * DMODEL;
        float v = g_qkv[base + t];
        float ss = v * v;
        #pragma unroll
        for (int off = 16; off; off >>= 1) ss += __shfl_xor_sync(0xffffffffu, ss, off);
        if (lane == 0) part[wrp] = ss;
        __syncthreads();
        float sumsq = part[2 * h] + part[2 * h + 1];
        float r = rsqrtf(sumsq * (1.0f / 64.0f) + 1e-6f);
        const float* ww = which ? kw : qw;
        float xn = v * r * ww[hd];
        sm[t] = xn;
        __syncthreads();
        float partner = sm[h * 64 + ((hd + 32) & 63)];
        float rot = (hd < 32) ? -partner : partner;
        g_qkv[base + t] = xn * cs + rot * sn;
        __syncthreads();
    }
}

// ---------------- 5) flash attention (fp32, TQ=32, TK=64, 128 threads) ----------------
#define QS_STRIDE 68
#define KT_STRIDE 65
#define VS_STRIDE 68
#define PS_STRIDE 68
#define ATTN_SMEM ((32 * QS_STRIDE + 64 * KT_STRIDE + 64 * VS_STRIDE + 32 * PS_STRIDE) * 4)

__global__ void __launch_bounds__(128)
attn_kernel() {
    extern __shared__ float smem[];
    float* qs  = smem;                       // [32][QS_STRIDE]
    float* ksT = qs + 32 * QS_STRIDE;        // [64][KT_STRIDE]  (d-major, transposed)
    float* vs  = ksT + 64 * KT_STRIDE;       // [64][VS_STRIDE]
    float* ps  = vs + 64 * VS_STRIDE;        // [32][PS_STRIDE]

    int qt = blockIdx.x, h = blockIdx.y, b = blockIdx.z;
    int t = threadIdx.x;
    int tr = t >> 4, tk = t & 15;            // 8 x 16 thread grid, 4x4 register tiles
    size_t qbase = (((size_t)(b * SEQ + qt * 32)) * 3 + 0) * DMODEL + h * HDIM;
    size_t kbase = (((size_t)(b * SEQ)) * 3 + 1) * DMODEL + h * HDIM;
    size_t vbase = kbase + DMODEL;
    const float scale = 0.125f;              // 1/sqrt(64)

    // load Q tile (pre-scaled)
    #pragma unroll
    for (int i = 0; i < 4; i++) {
        int f = t + i * 128;
        int r = f >> 4, c4 = (f & 15) * 4;
        float4 v = *(const float4*)(&g_qkv[qbase + (size_t)r * 3 * DMODEL + c4]);
        v.x *= scale; v.y *= scale; v.z *= scale; v.w *= scale;
        *(float4*)&qs[r * QS_STRIDE + c4] = v;
    }

    float o[4][4], m[4], l[4];
    #pragma unroll
    for (int i = 0; i < 4; i++) {
        m[i] = -1e30f; l[i] = 0.0f;
        #pragma unroll
        for (int j = 0; j < 4; j++) o[i][j] = 0.0f;
    }

    for (int k0 = 0; k0 < SEQ; k0 += 64) {
        __syncthreads();  // previous iteration consumers done before overwrite
        #pragma unroll
        for (int i = 0; i < 8; i++) {
            int f = t + i * 128;
            int r = f >> 4, c4 = (f & 15) * 4;
            float4 kv = *(const float4*)(&g_qkv[kbase + (size_t)(k0 + r) * 3 * DMODEL + c4]);
            ksT[(c4 + 0) * KT_STRIDE + r] = kv.x;
            ksT[(c4 + 1) * KT_STRIDE + r] = kv.y;
            ksT[(c4 + 2) * KT_STRIDE + r] = kv.z;
            ksT[(c4 + 3) * KT_STRIDE + r] = kv.w;
            float4 vv = *(const float4*)(&g_qkv[vbase + (size_t)(k0 + r) * 3 * DMODEL + c4]);
            *(float4*)&vs[r * VS_STRIDE + c4] = vv;
        }
        __syncthreads();

        // scores S = Q K^T (4x4 per thread)
        float sc[4][4];
        #pragma unroll
        for (int i = 0; i < 4; i++)
            #pragma unroll
            for (int j = 0; j < 4; j++) sc[i][j] = 0.0f;
        #pragma unroll 8
        for (int d = 0; d < 64; d++) {
            float qv[4], kv[4];
            #pragma unroll
            for (int i = 0; i < 4; i++) qv[i] = qs[(tr * 4 + i) * QS_STRIDE + d];
            #pragma unroll
            for (int j = 0; j < 4; j++) kv[j] = ksT[d * KT_STRIDE + tk * 4 + j];
            #pragma unroll
            for (int i = 0; i < 4; i++)
                #pragma unroll
                for (int j = 0; j < 4; j++) sc[i][j] += qv[i] * kv[j];
        }

        // online softmax update (row shared by 16 lanes within each warp)
        #pragma unroll
        for (int i = 0; i < 4; i++) {
            float mx = sc[i][0];
            #pragma unroll
            for (int j = 1; j < 4; j++) mx = fmaxf(mx, sc[i][j]);
            #pragma unroll
            for (int off = 1; off < 16; off <<= 1)
                mx = fmaxf(mx, __shfl_xor_sync(0xffffffffu, mx, off));
            float mn = fmaxf(m[i], mx);
            float alpha = __expf(m[i] - mn);
            float lloc = 0.0f;
            #pragma unroll
            for (int j = 0; j < 4; j++) {
                float p = __expf(sc[i][j] - mn);
                sc[i][j] = p;
                lloc += p;
            }
            #pragma unroll
            for (int off = 1; off < 16; off <<= 1)
                lloc += __shfl_xor_sync(0xffffffffu, lloc, off);
            l[i] = l[i] * alpha + lloc;
            m[i] = mn;
            #pragma unroll
            for (int j = 0; j < 4; j++) o[i][j] *= alpha;
            #pragma unroll
            for (int j = 0; j < 4; j++) ps[(tr * 4 + i) * PS_STRIDE + tk * 4 + j] = sc[i][j];
        }
        __syncthreads();

        // O += P V  (4x4 per thread)
        #pragma unroll 8
        for (int k = 0; k < 64; k++) {
            float pv[4], vv[4];
            #pragma unroll
            for (int i = 0; i < 4; i++) pv[i] = ps[(tr * 4 + i) * PS_STRIDE + k];
            #pragma unroll
            for (int j = 0; j < 4; j++) vv[j] = vs[k * VS_STRIDE + tk * 4 + j];
            #pragma unroll
            for (int i = 0; i < 4; i++)
                #pragma unroll
                for (int j = 0; j < 4; j++) o[i][j] += pv[i] * vv[j];
        }
    }

    #pragma unroll
    for (int i = 0; i < 4; i++) {
        float inv = 1.0f / l[i];
        int r = qt * 32 + tr * 4 + i;
        size_t ob = ((size_t)(b * SEQ + r)) * DMODEL + h * HDIM + tk * 4;
        #pragma unroll
        for (int j = 0; j < 4; j++) g_attn[ob + j] = o[i][j] * inv;
    }
}

// ---------------- launch ----------------
extern "C" void kernel_launch(void* const* d_in, const int* in_sizes, int n_in,
                              void* d_out, int out_size) {
    const float* x       = (const float*)d_in[0];
    const float* cosb    = (const float*)d_in[1];
    const float* sinb    = (const float*)d_in[2];
    const float* c       = (const float*)d_in[3];
    const float* norm1_w = (const float*)d_in[4];
    const float* Wqkv    = (const float*)d_in[5];
    const float* Wout    = (const float*)d_in[6];
    const float* q_norm_w = (const float*)d_in[7];
    const float* k_norm_w = (const float*)d_in[8];
    const float* norm2_w = (const float*)d_in[9];
    const float* W1      = (const float*)d_in[10];
    const float* b1      = (const float*)d_in[11];
    const float* W2      = (const float*)d_in[12];
    const float* b2      = (const float*)d_in[13];
    const float* ada_W   = (const float*)d_in[14];
    const float* ada_b   = (const float*)d_in[15];
    float* out = (float*)d_out;

    float *p_mod, *p_xn, *p_qkv, *p_attn, *p_x2, *p_h;
    cudaGetSymbolAddress((void**)&p_mod, g_mod);
    cudaGetSymbolAddress((void**)&p_xn, g_xn);
    cudaGetSymbolAddress((void**)&p_qkv, g_qkv);
    cudaGetSymbolAddress((void**)&p_attn, g_attn);
    cudaGetSymbolAddress((void**)&p_x2, g_x2);
    cudaGetSymbolAddress((void**)&p_h, g_h);

    cudaFuncSetAttribute(attn_kernel, cudaFuncAttributeMaxDynamicSharedMemorySize, ATTN_SMEM);

    // 1) adaLN modulation vectors
    mod_kernel<<<dim3(MODW / 256, BATCH), 256>>>(c, ada_W, ada_b);
    // 2) LN1 + modulate
    ln_mod_kernel<<<NROWS, 256>>>(x, norm1_w, 0, 1024, p_xn);
    // 3) qkv = xn @ Wqkv
    sgemm_kernel<0><<<dim3(3 * DMODEL / 128, NROWS / 128), 256>>>(
        p_xn, Wqkv, p_qkv, NROWS, 3 * DMODEL, DMODEL, nullptr, nullptr, nullptr);
    // 4) rmsnorm + rope on q,k (in place)
    rope_kernel<<<NROWS, 1024>>>(q_norm_w, k_norm_w, cosb, sinb);
    // 5) attention
    attn_kernel<<<dim3(SEQ / 32, NHEADS, BATCH), 128, ATTN_SMEM>>>();
    // 6) x2 = x + g_msa * (attn @ Wout)
    sgemm_kernel<1><<<dim3(DMODEL / 128, NROWS / 128), 256>>>(
        p_attn, Wout, p_x2, NROWS, DMODEL, DMODEL, x, nullptr, p_mod + 2 * 1024);
    // 7) LN2 + modulate
    ln_mod_kernel<<<NROWS, 256>>>(p_x2, norm2_w, 3 * 1024, 4 * 1024, p_xn);
    // 8) h = gelu(xn @ W1 + b1)
    sgemm_kernel<2><<<dim3(DFF / 128, NROWS / 128), 256>>>(
        p_xn, W1, p_h, NROWS, DFF, DMODEL, nullptr, b1, nullptr);
    // 9) out = x2 + g_mlp * (h @ W2 + b2)
    sgemm_kernel<3><<<dim3(DMODEL / 128, NROWS / 128), 256>>>(
        p_h, W2, out, NROWS, DMODEL, DFF, p_x2, b2, p_mod + 5 * 1024);
}

// round 5
// speedup vs baseline: 1.9049x; 1.9049x over previous
#include <cuda_runtime.h>
#include <math.h>
#include <stdint.h>

#define DMODEL 1024
#define SEQ    2048
#define BATCH  4
#define NHEADS 16
#define HDIM   64
#define DFF    4096
#define NROWS  8192      // BATCH*SEQ
#define MODW   6144

// ---------------- scratch (static device arrays; no allocation) ----------------
__device__ float g_mod[BATCH * MODW];
__device__ float g_xn[(size_t)NROWS * DMODEL];
__device__ float g_qkv[(size_t)NROWS * 3 * DMODEL];
__device__ float g_attn[(size_t)NROWS * DMODEL];
__device__ float g_x2[(size_t)NROWS * DMODEL];
__device__ float g_h[(size_t)NROWS * DFF];

// ---------------- helpers ----------------
__device__ __forceinline__ float gelu_tanh(float x) {
    float x3 = x * x * x;
    float u = 0.7978845608028654f * (x + 0.044715f * x3);
    return 0.5f * x * (1.0f + tanhf(u));
}

__device__ __forceinline__ uint32_t f2tf(float f) {
    uint32_t u;
    asm("cvt.rna.tf32.f32 %0, %1;" : "=r"(u) : "f"(f));
    return u;
}

__device__ __forceinline__ void mma_tf32(float c[4], const uint32_t a[4], const uint32_t b[2]) {
    asm volatile(
        "mma.sync.aligned.m16n8k8.row.col.f32.tf32.tf32.f32 "
        "{%0,%1,%2,%3}, {%4,%5,%6,%7}, {%8,%9}, {%0,%1,%2,%3};\n"
        : "+f"(c[0]), "+f"(c[1]), "+f"(c[2]), "+f"(c[3])
        : "r"(a[0]), "r"(a[1]), "r"(a[2]), "r"(a[3]), "r"(b[0]), "r"(b[1]));
}

__device__ __forceinline__ void blockReduce2(float& a, float& b) {
    #pragma unroll
    for (int off = 16; off; off >>= 1) {
        a += __shfl_xor_sync(0xffffffffu, a, off);
        b += __shfl_xor_sync(0xffffffffu, b, off);
    }
    __shared__ float sa[8], sb[8];
    int w = threadIdx.x >> 5, l = threadIdx.x & 31;
    if (l == 0) { sa[w] = a; sb[w] = b; }
    __syncthreads();
    if (w == 0) {
        a = (l < 8) ? sa[l] : 0.0f;
        b = (l < 8) ? sb[l] : 0.0f;
        #pragma unroll
        for (int off = 4; off; off >>= 1) {
            a += __shfl_xor_sync(0xffffffffu, a, off);
            b += __shfl_xor_sync(0xffffffffu, b, off);
        }
        if (l == 0) { sa[0] = a; sb[0] = b; }
    }
    __syncthreads();
    a = sa[0]; b = sb[0];
}

// ---------------- 1) mod = c @ ada_W + ada_b ----------------
__global__ void mod_kernel(const float* __restrict__ c, const float* __restrict__ W,
                           const float* __restrict__ bias) {
    __shared__ float cs[1024];
    int b = blockIdx.y;
    int col = blockIdx.x * 256 + threadIdx.x;
    for (int i = threadIdx.x; i < 1024; i += 256) cs[i] = c[b * 1024 + i];
    __syncthreads();
    float acc = 0.0f;
    #pragma unroll 4
    for (int k = 0; k < 1024; k++) acc += cs[k] * W[(size_t)k * MODW + col];
    g_mod[b * MODW + col] = acc + bias[col];
}

// ---------------- 2) layernorm + modulate ----------------
__global__ void ln_mod_kernel(const float* __restrict__ X, const float* __restrict__ w,
                              int shOff, int scOff, float* __restrict__ out) {
    int row = blockIdx.x;
    int b = row >> 11;
    const float4* xr = (const float4*)(X + (size_t)row * DMODEL);
    float4 v = xr[threadIdx.x];
    float s = v.x + v.y + v.z + v.w;
    float ss = v.x * v.x + v.y * v.y + v.z * v.z + v.w * v.w;
    blockReduce2(s, ss);
    float mu = s * (1.0f / 1024.0f);
    float var = ss * (1.0f / 1024.0f) - mu * mu;
    float r = rsqrtf(var + 1e-5f);
    int d = threadIdx.x * 4;
    const float* mb = g_mod + b * MODW;
    float4 o;
    o.x = (v.x - mu) * r * w[d + 0] * (1.0f + mb[scOff + d + 0]) + mb[shOff + d + 0];
    o.y = (v.y - mu) * r * w[d + 1] * (1.0f + mb[scOff + d + 1]) + mb[shOff + d + 1];
    o.z = (v.z - mu) * r * w[d + 2] * (1.0f + mb[scOff + d + 2]) + mb[shOff + d + 2];
    o.w = (v.w - mu) * r * w[d + 3] * (1.0f + mb[scOff + d + 3]) + mb[shOff + d + 3];
    ((float4*)(out + (size_t)row * DMODEL))[threadIdx.x] = o;
}

// ---------------- 3) TF32 tensor-core GEMM, 128x128x16, cp.async double buffer --------
// MODE 0: C = acc
// MODE 1: C = res + gate[b][col] * acc
// MODE 2: C = gelu(acc + bias[col])
// MODE 3: C = res + gate[b][col] * (acc + bias[col])
#define AS_STRIDE 20
#define BS_STRIDE 136

template<int MODE>
__global__ void __launch_bounds__(256, 2)
mma_gemm(const float* __restrict__ A, const float* __restrict__ B, float* __restrict__ C,
         int M, int N, int K,
         const float* __restrict__ res, const float* __restrict__ bias,
         const float* __restrict__ gate) {
    __shared__ float As[2][128 * AS_STRIDE];
    __shared__ float Bs[2][16 * BS_STRIDE];
    const int t = threadIdx.x;
    const int lane = t & 31, wid = t >> 5;
    const int warp_m = wid & 1, warp_n = wid >> 1;   // 2 x 4 warp grid
    const int rowBase = blockIdx.y * 128, colBase = blockIdx.x * 128;

    const int nk = K >> 4;

    float acc[4][4][4];
    #pragma unroll
    for (int mt = 0; mt < 4; mt++)
        #pragma unroll
        for (int nt = 0; nt < 4; nt++)
            #pragma unroll
            for (int f = 0; f < 4; f++) acc[mt][nt][f] = 0.0f;

    auto load_stage = [&](int kt, int buf) {
        #pragma unroll
        for (int i = 0; i < 2; i++) {
            int idx = t + i * 256;           // 0..511
            int r = idx >> 2, q = idx & 3;   // 128 rows x 4 k-quads
            const float* src = A + (size_t)(rowBase + r) * K + kt * 16 + q * 4;
            uint32_t dst = (uint32_t)__cvta_generic_to_shared(&As[buf][r * AS_STRIDE + q * 4]);
            asm volatile("cp.async.cg.shared.global [%0], [%1], 16;" :: "r"(dst), "l"(src) : "memory");
        }
        #pragma unroll
        for (int i = 0; i < 2; i++) {
            int idx = t + i * 256;           // 0..511
            int k = idx >> 5, cq = idx & 31; // 16 k-rows x 32 col-quads
            const float* src = B + (size_t)(kt * 16 + k) * N + colBase + cq * 4;
            uint32_t dst = (uint32_t)__cvta_generic_to_shared(&Bs[buf][k * BS_STRIDE + cq * 4]);
            asm volatile("cp.async.cg.shared.global [%0], [%1], 16;" :: "r"(dst), "l"(src) : "memory");
        }
        asm volatile("cp.async.commit_group;" ::: "memory");
    };

    load_stage(0, 0);
    for (int kt = 0; kt < nk; kt++) {
        if (kt + 1 < nk) {
            load_stage(kt + 1, (kt + 1) & 1);
            asm volatile("cp.async.wait_group 1;" ::: "memory");
        } else {
            asm volatile("cp.async.wait_group 0;" ::: "memory");
        }
        __syncthreads();
        const float* as = As[kt & 1];
        const float* bs = Bs[kt & 1];
        #pragma unroll
        for (int ks = 0; ks < 2; ks++) {
            const int k0 = ks * 8;
            uint32_t af[4][4], bf[4][2];
            const int kk = k0 + (lane & 3);
            #pragma unroll
            for (int mt = 0; mt < 4; mt++) {
                int m0 = warp_m * 64 + mt * 16 + (lane >> 2);
                af[mt][0] = f2tf(as[(m0    ) * AS_STRIDE + kk    ]);
                af[mt][1] = f2tf(as[(m0 + 8) * AS_STRIDE + kk    ]);
                af[mt][2] = f2tf(as[(m0    ) * AS_STRIDE + kk + 4]);
                af[mt][3] = f2tf(as[(m0 + 8) * AS_STRIDE + kk + 4]);
            }
            #pragma unroll
            for (int nt = 0; nt < 4; nt++) {
                int n0 = warp_n * 32 + nt * 8 + (lane >> 2);
                bf[nt][0] = f2tf(bs[(kk    ) * BS_STRIDE + n0]);
                bf[nt][1] = f2tf(bs[(kk + 4) * BS_STRIDE + n0]);
            }
            #pragma unroll
            for (int mt = 0; mt < 4; mt++)
                #pragma unroll
                for (int nt = 0; nt < 4; nt++)
                    mma_tf32(acc[mt][nt], af[mt], bf[nt]);
        }
        __syncthreads();
    }

    #pragma unroll
    for (int mt = 0; mt < 4; mt++) {
        #pragma unroll
        for (int nt = 0; nt < 4; nt++) {
            #pragma unroll
            for (int half = 0; half < 2; half++) {
                int gr = rowBase + warp_m * 64 + mt * 16 + (lane >> 2) + half * 8;
                int gc = colBase + warp_n * 32 + nt * 8 + (lane & 3) * 2;
                int bb = gr >> 11;
                size_t off = (size_t)gr * N + gc;
                float v0 = acc[mt][nt][half * 2 + 0];
                float v1 = acc[mt][nt][half * 2 + 1];
                if (MODE == 0) {
                    C[off] = v0; C[off + 1] = v1;
                } else if (MODE == 1) {
                    C[off]     = res[off]     + gate[bb * MODW + gc]     * v0;
                    C[off + 1] = res[off + 1] + gate[bb * MODW + gc + 1] * v1;
                } else if (MODE == 2) {
                    C[off]     = gelu_tanh(v0 + bias[gc]);
                    C[off + 1] = gelu_tanh(v1 + bias[gc + 1]);
                } else {
                    C[off]     = res[off]     + gate[bb * MODW + gc]     * (v0 + bias[gc]);
                    C[off + 1] = res[off + 1] + gate[bb * MODW + gc + 1] * (v1 + bias[gc + 1]);
                }
            }
        }
    }
}

// ---------------- 4) per-head rmsnorm + rope on q,k (in place in g_qkv) ----------------
__global__ void __launch_bounds__(1024)
rope_kernel(const float* __restrict__ qw, const float* __restrict__ kw,
            const float* __restrict__ cosb, const float* __restrict__ sinb) {
    __shared__ float sm[1024];
    __shared__ float part[32];
    int row = blockIdx.x;            // b*SEQ + s
    int s = row & (SEQ - 1);
    int t = threadIdx.x;             // 1024 threads
    int h = t >> 6, hd = t & 63;
    int wrp = t >> 5, lane = t & 31;
    float cs = cosb[s * HDIM + hd], sn = sinb[s * HDIM + hd];
    #pragma unroll
    for (int which = 0; which < 2; which++) {
        size_t base = ((size_t)row * 3 + which) * DMODEL;
        float v = g_qkv[base + t];
        float ss = v * v;
        #pragma unroll
        for (int off = 16; off; off >>= 1) ss += __shfl_xor_sync(0xffffffffu, ss, off);
        if (lane == 0) part[wrp] = ss;
        __syncthreads();
        float sumsq = part[2 * h] + part[2 * h + 1];
        float r = rsqrtf(sumsq * (1.0f / 64.0f) + 1e-6f);
        const float* ww = which ? kw : qw;
        float xn = v * r * ww[hd];
        sm[t] = xn;
        __syncthreads();
        float partner = sm[h * 64 + ((hd + 32) & 63)];
        float rot = (hd < 32) ? -partner : partner;
        g_qkv[base + t] = xn * cs + rot * sn;
        __syncthreads();
    }
}

// ---------------- 5) flash attention (fp32, TQ=32, TK=64, 128 threads) ----------------
#define QS_STRIDE 68
#define KT_STRIDE 65
#define VS_STRIDE 68
#define PS_STRIDE 68
#define ATTN_SMEM ((32 * QS_STRIDE + 64 * KT_STRIDE + 64 * VS_STRIDE + 32 * PS_STRIDE) * 4)

__global__ void __launch_bounds__(128)
attn_kernel() {
    extern __shared__ float smem[];
    float* qs  = smem;                       // [32][QS_STRIDE]
    float* ksT = qs + 32 * QS_STRIDE;        // [64][KT_STRIDE]
    float* vs  = ksT + 64 * KT_STRIDE;       // [64][VS_STRIDE]
    float* ps  = vs + 64 * VS_STRIDE;        // [32][PS_STRIDE]

    int qt = blockIdx.x, h = blockIdx.y, b = blockIdx.z;
    int t = threadIdx.x;
    int tr = t >> 4, tk = t & 15;
    size_t qbase = (((size_t)(b * SEQ + qt * 32)) * 3 + 0) * DMODEL + h * HDIM;
    size_t kbase = (((size_t)(b * SEQ)) * 3 + 1) * DMODEL + h * HDIM;
    size_t vbase = kbase + DMODEL;
    const float scale = 0.125f;

    #pragma unroll
    for (int i = 0; i < 4; i++) {
        int f = t + i * 128;
        int r = f >> 4, c4 = (f & 15) * 4;
        float4 v = *(const float4*)(&g_qkv[qbase + (size_t)r * 3 * DMODEL + c4]);
        v.x *= scale; v.y *= scale; v.z *= scale; v.w *= scale;
        *(float4*)&qs[r * QS_STRIDE + c4] = v;
    }

    float o[4][4], m[4], l[4];
    #pragma unroll
    for (int i = 0; i < 4; i++) {
        m[i] = -1e30f; l[i] = 0.0f;
        #pragma unroll
        for (int j = 0; j < 4; j++) o[i][j] = 0.0f;
    }

    for (int k0 = 0; k0 < SEQ; k0 += 64) {
        __syncthreads();
        #pragma unroll
        for (int i = 0; i < 8; i++) {
            int f = t + i * 128;
            int r = f >> 4, c4 = (f & 15) * 4;
            float4 kv = *(const float4*)(&g_qkv[kbase + (size_t)(k0 + r) * 3 * DMODEL + c4]);
            ksT[(c4 + 0) * KT_STRIDE + r] = kv.x;
            ksT[(c4 + 1) * KT_STRIDE + r] = kv.y;
            ksT[(c4 + 2) * KT_STRIDE + r] = kv.z;
            ksT[(c4 + 3) * KT_STRIDE + r] = kv.w;
            float4 vv = *(const float4*)(&g_qkv[vbase + (size_t)(k0 + r) * 3 * DMODEL + c4]);
            *(float4*)&vs[r * VS_STRIDE + c4] = vv;
        }
        __syncthreads();

        float sc[4][4];
        #pragma unroll
        for (int i = 0; i < 4; i++)
            #pragma unroll
            for (int j = 0; j < 4; j++) sc[i][j] = 0.0f;
        #pragma unroll 8
        for (int d = 0; d < 64; d++) {
            float qv[4], kv[4];
            #pragma unroll
            for (int i = 0; i < 4; i++) qv[i] = qs[(tr * 4 + i) * QS_STRIDE + d];
            #pragma unroll
            for (int j = 0; j < 4; j++) kv[j] = ksT[d * KT_STRIDE + tk * 4 + j];
            #pragma unroll
            for (int i = 0; i < 4; i++)
                #pragma unroll
                for (int j = 0; j < 4; j++) sc[i][j] += qv[i] * kv[j];
        }

        #pragma unroll
        for (int i = 0; i < 4; i++) {
            float mx = sc[i][0];
            #pragma unroll
            for (int j = 1; j < 4; j++) mx = fmaxf(mx, sc[i][j]);
            #pragma unroll
            for (int off = 1; off < 16; off <<= 1)
                mx = fmaxf(mx, __shfl_xor_sync(0xffffffffu, mx, off));
            float mn = fmaxf(m[i], mx);
            float alpha = __expf(m[i] - mn);
            float lloc = 0.0f;
            #pragma unroll
            for (int j = 0; j < 4; j++) {
                float p = __expf(sc[i][j] - mn);
                sc[i][j] = p;
                lloc += p;
            }
            #pragma unroll
            for (int off = 1; off < 16; off <<= 1)
                lloc += __shfl_xor_sync(0xffffffffu, lloc, off);
            l[i] = l[i] * alpha + lloc;
            m[i] = mn;
            #pragma unroll
            for (int j = 0; j < 4; j++) o[i][j] *= alpha;
            #pragma unroll
            for (int j = 0; j < 4; j++) ps[(tr * 4 + i) * PS_STRIDE + tk * 4 + j] = sc[i][j];
        }
        __syncthreads();

        #pragma unroll 8
        for (int k = 0; k < 64; k++) {
            float pv[4], vv[4];
            #pragma unroll
            for (int i = 0; i < 4; i++) pv[i] = ps[(tr * 4 + i) * PS_STRIDE + k];
            #pragma unroll
            for (int j = 0; j < 4; j++) vv[j] = vs[k * VS_STRIDE + tk * 4 + j];
            #pragma unroll
            for (int i = 0; i < 4; i++)
                #pragma unroll
                for (int j = 0; j < 4; j++) o[i][j] += pv[i] * vv[j];
        }
    }

    #pragma unroll
    for (int i = 0; i < 4; i++) {
        float inv = 1.0f / l[i];
        int r = qt * 32 + tr * 4 + i;
        size_t ob = ((size_t)(b * SEQ + r)) * DMODEL + h * HDIM + tk * 4;
        #pragma unroll
        for (int j = 0; j < 4; j++) g_attn[ob + j] = o[i][j] * inv;
    }
}

// ---------------- launch ----------------
extern "C" void kernel_launch(void* const* d_in, const int* in_sizes, int n_in,
                              void* d_out, int out_size) {
    const float* x       = (const float*)d_in[0];
    const float* cosb    = (const float*)d_in[1];
    const float* sinb    = (const float*)d_in[2];
    const float* c       = (const float*)d_in[3];
    const float* norm1_w = (const float*)d_in[4];
    const float* Wqkv    = (const float*)d_in[5];
    const float* Wout    = (const float*)d_in[6];
    const float* q_norm_w = (const float*)d_in[7];
    const float* k_norm_w = (const float*)d_in[8];
    const float* norm2_w = (const float*)d_in[9];
    const float* W1      = (const float*)d_in[10];
    const float* b1      = (const float*)d_in[11];
    const float* W2      = (const float*)d_in[12];
    const float* b2      = (const float*)d_in[13];
    const float* ada_W   = (const float*)d_in[14];
    const float* ada_b   = (const float*)d_in[15];
    float* out = (float*)d_out;

    float *p_mod, *p_xn, *p_qkv, *p_attn, *p_x2, *p_h;
    cudaGetSymbolAddress((void**)&p_mod, g_mod);
    cudaGetSymbolAddress((void**)&p_xn, g_xn);
    cudaGetSymbolAddress((void**)&p_qkv, g_qkv);
    cudaGetSymbolAddress((void**)&p_attn, g_attn);
    cudaGetSymbolAddress((void**)&p_x2, g_x2);
    cudaGetSymbolAddress((void**)&p_h, g_h);

    cudaFuncSetAttribute(attn_kernel, cudaFuncAttributeMaxDynamicSharedMemorySize, ATTN_SMEM);

    // 1) adaLN modulation vectors
    mod_kernel<<<dim3(MODW / 256, BATCH), 256>>>(c, ada_W, ada_b);
    // 2) LN1 + modulate
    ln_mod_kernel<<<NROWS, 256>>>(x, norm1_w, 0, 1024, p_xn);
    // 3) qkv = xn @ Wqkv   (TF32 tensor cores)
    mma_gemm<0><<<dim3(3 * DMODEL / 128, NROWS / 128), 256>>>(
        p_xn, Wqkv, p_qkv, NROWS, 3 * DMODEL, DMODEL, nullptr, nullptr, nullptr);
    // 4) rmsnorm + rope on q,k (in place)
    rope_kernel<<<NROWS, 1024>>>(q_norm_w, k_norm_w, cosb, sinb);
    // 5) attention
    attn_kernel<<<dim3(SEQ / 32, NHEADS, BATCH), 128, ATTN_SMEM>>>();
    // 6) x2 = x + g_msa * (attn @ Wout)
    mma_gemm<1><<<dim3(DMODEL / 128, NROWS / 128), 256>>>(
        p_attn, Wout, p_x2, NROWS, DMODEL, DMODEL, x, nullptr, p_mod + 2 * 1024);
    // 7) LN2 + modulate
    ln_mod_kernel<<<NROWS, 256>>>(p_x2, norm2_w, 3 * 1024, 4 * 1024, p_xn);
    // 8) h = gelu(xn @ W1 + b1)
    mma_gemm<2><<<dim3(DFF / 128, NROWS / 128), 256>>>(
        p_xn, W1, p_h, NROWS, DFF, DMODEL, nullptr, b1, nullptr);
    // 9) out = x2 + g_mlp * (h @ W2 + b2)
    mma_gemm<3><<<dim3(DMODEL / 128, NROWS / 128), 256>>>(
        p_h, W2, out, NROWS, DMODEL, DFF, p_x2, b2, p_mod + 5 * 1024);
}

// round 6
// speedup vs baseline: 2.8648x; 1.5039x over previous
#include <cuda_runtime.h>
#include <math.h>
#include <stdint.h>

#define DMODEL 1024
#define SEQ    2048
#define BATCH  4
#define NHEADS 16
#define HDIM   64
#define DFF    4096
#define NROWS  8192      // BATCH*SEQ
#define MODW   6144

// ---------------- scratch (static device arrays; no allocation) ----------------
__device__ float g_mod[BATCH * MODW];
__device__ float g_xn[(size_t)NROWS * DMODEL];
__device__ float g_qkv[(size_t)NROWS * 3 * DMODEL];
__device__ float g_attn[(size_t)NROWS * DMODEL];
__device__ float g_x2[(size_t)NROWS * DMODEL];
__device__ float g_h[(size_t)NROWS * DFF];

// ---------------- helpers ----------------
__device__ __forceinline__ float gelu_tanh(float x) {
    float x3 = x * x * x;
    float u = 0.7978845608028654f * (x + 0.044715f * x3);
    return 0.5f * x * (1.0f + tanhf(u));
}

__device__ __forceinline__ uint32_t f2tf(float f) {
    uint32_t u;
    asm("cvt.rna.tf32.f32 %0, %1;" : "=r"(u) : "f"(f));
    return u;
}

__device__ __forceinline__ float ex2(float x) {
    float r;
    asm("ex2.approx.ftz.f32 %0, %1;" : "=f"(r) : "f"(x));
    return r;
}

__device__ __forceinline__ void mma_tf32(float c[4], const uint32_t a[4], const uint32_t b[2]) {
    asm volatile(
        "mma.sync.aligned.m16n8k8.row.col.f32.tf32.tf32.f32 "
        "{%0,%1,%2,%3}, {%4,%5,%6,%7}, {%8,%9}, {%0,%1,%2,%3};\n"
        : "+f"(c[0]), "+f"(c[1]), "+f"(c[2]), "+f"(c[3])
        : "r"(a[0]), "r"(a[1]), "r"(a[2]), "r"(a[3]), "r"(b[0]), "r"(b[1]));
}

__device__ __forceinline__ void blockReduce2(float& a, float& b) {
    #pragma unroll
    for (int off = 16; off; off >>= 1) {
        a += __shfl_xor_sync(0xffffffffu, a, off);
        b += __shfl_xor_sync(0xffffffffu, b, off);
    }
    __shared__ float sa[8], sb[8];
    int w = threadIdx.x >> 5, l = threadIdx.x & 31;
    if (l == 0) { sa[w] = a; sb[w] = b; }
    __syncthreads();
    if (w == 0) {
        a = (l < 8) ? sa[l] : 0.0f;
        b = (l < 8) ? sb[l] : 0.0f;
        #pragma unroll
        for (int off = 4; off; off >>= 1) {
            a += __shfl_xor_sync(0xffffffffu, a, off);
            b += __shfl_xor_sync(0xffffffffu, b, off);
        }
        if (l == 0) { sa[0] = a; sb[0] = b; }
    }
    __syncthreads();
    a = sa[0]; b = sb[0];
}

// ---------------- 1) mod = c @ ada_W + ada_b ----------------
__global__ void mod_kernel(const float* __restrict__ c, const float* __restrict__ W,
                           const float* __restrict__ bias) {
    __shared__ float cs[1024];
    int b = blockIdx.y;
    int col = blockIdx.x * 256 + threadIdx.x;
    for (int i = threadIdx.x; i < 1024; i += 256) cs[i] = c[b * 1024 + i];
    __syncthreads();
    float acc = 0.0f;
    #pragma unroll 4
    for (int k = 0; k < 1024; k++) acc += cs[k] * W[(size_t)k * MODW + col];
    g_mod[b * MODW + col] = acc + bias[col];
}

// ---------------- 2) layernorm + modulate ----------------
__global__ void ln_mod_kernel(const float* __restrict__ X, const float* __restrict__ w,
                              int shOff, int scOff, float* __restrict__ out) {
    int row = blockIdx.x;
    int b = row >> 11;
    const float4* xr = (const float4*)(X + (size_t)row * DMODEL);
    float4 v = xr[threadIdx.x];
    float s = v.x + v.y + v.z + v.w;
    float ss = v.x * v.x + v.y * v.y + v.z * v.z + v.w * v.w;
    blockReduce2(s, ss);
    float mu = s * (1.0f / 1024.0f);
    float var = ss * (1.0f / 1024.0f) - mu * mu;
    float r = rsqrtf(var + 1e-5f);
    int d = threadIdx.x * 4;
    const float* mb = g_mod + b * MODW;
    float4 o;
    o.x = (v.x - mu) * r * w[d + 0] * (1.0f + mb[scOff + d + 0]) + mb[shOff + d + 0];
    o.y = (v.y - mu) * r * w[d + 1] * (1.0f + mb[scOff + d + 1]) + mb[shOff + d + 1];
    o.z = (v.z - mu) * r * w[d + 2] * (1.0f + mb[scOff + d + 2]) + mb[shOff + d + 2];
    o.w = (v.w - mu) * r * w[d + 3] * (1.0f + mb[scOff + d + 3]) + mb[shOff + d + 3];
    ((float4*)(out + (size_t)row * DMODEL))[threadIdx.x] = o;
}

// ---------------- 3) TF32 tensor-core GEMM, 128x128x16, cp.async double buffer --------
#define AS_STRIDE 20
#define BS_STRIDE 136

template<int MODE>
__global__ void __launch_bounds__(256, 2)
mma_gemm(const float* __restrict__ A, const float* __restrict__ B, float* __restrict__ C,
         int M, int N, int K,
         const float* __restrict__ res, const float* __restrict__ bias,
         const float* __restrict__ gate) {
    __shared__ float As[2][128 * AS_STRIDE];
    __shared__ float Bs[2][16 * BS_STRIDE];
    const int t = threadIdx.x;
    const int lane = t & 31, wid = t >> 5;
    const int warp_m = wid & 1, warp_n = wid >> 1;   // 2 x 4 warp grid
    const int rowBase = blockIdx.y * 128, colBase = blockIdx.x * 128;

    const int nk = K >> 4;

    float acc[4][4][4];
    #pragma unroll
    for (int mt = 0; mt < 4; mt++)
        #pragma unroll
        for (int nt = 0; nt < 4; nt++)
            #pragma unroll
            for (int f = 0; f < 4; f++) acc[mt][nt][f] = 0.0f;

    auto load_stage = [&](int kt, int buf) {
        #pragma unroll
        for (int i = 0; i < 2; i++) {
            int idx = t + i * 256;           // 0..511
            int r = idx >> 2, q = idx & 3;   // 128 rows x 4 k-quads
            const float* src = A + (size_t)(rowBase + r) * K + kt * 16 + q * 4;
            uint32_t dst = (uint32_t)__cvta_generic_to_shared(&As[buf][r * AS_STRIDE + q * 4]);
            asm volatile("cp.async.cg.shared.global [%0], [%1], 16;" :: "r"(dst), "l"(src) : "memory");
        }
        #pragma unroll
        for (int i = 0; i < 2; i++) {
            int idx = t + i * 256;           // 0..511
            int k = idx >> 5, cq = idx & 31; // 16 k-rows x 32 col-quads
            const float* src = B + (size_t)(kt * 16 + k) * N + colBase + cq * 4;
            uint32_t dst = (uint32_t)__cvta_generic_to_shared(&Bs[buf][k * BS_STRIDE + cq * 4]);
            asm volatile("cp.async.cg.shared.global [%0], [%1], 16;" :: "r"(dst), "l"(src) : "memory");
        }
        asm volatile("cp.async.commit_group;" ::: "memory");
    };

    load_stage(0, 0);
    for (int kt = 0; kt < nk; kt++) {
        if (kt + 1 < nk) {
            load_stage(kt + 1, (kt + 1) & 1);
            asm volatile("cp.async.wait_group 1;" ::: "memory");
        } else {
            asm volatile("cp.async.wait_group 0;" ::: "memory");
        }
        __syncthreads();
        const float* as = As[kt & 1];
        const float* bs = Bs[kt & 1];
        #pragma unroll
        for (int ks = 0; ks < 2; ks++) {
            const int k0 = ks * 8;
            uint32_t af[4][4], bf[4][2];
            const int kk = k0 + (lane & 3);
            #pragma unroll
            for (int mt = 0; mt < 4; mt++) {
                int m0 = warp_m * 64 + mt * 16 + (lane >> 2);
                af[mt][0] = f2tf(as[(m0    ) * AS_STRIDE + kk    ]);
                af[mt][1] = f2tf(as[(m0 + 8) * AS_STRIDE + kk    ]);
                af[mt][2] = f2tf(as[(m0    ) * AS_STRIDE + kk + 4]);
                af[mt][3] = f2tf(as[(m0 + 8) * AS_STRIDE + kk + 4]);
            }
            #pragma unroll
            for (int nt = 0; nt < 4; nt++) {
                int n0 = warp_n * 32 + nt * 8 + (lane >> 2);
                bf[nt][0] = f2tf(bs[(kk    ) * BS_STRIDE + n0]);
                bf[nt][1] = f2tf(bs[(kk + 4) * BS_STRIDE + n0]);
            }
            #pragma unroll
            for (int mt = 0; mt < 4; mt++)
                #pragma unroll
                for (int nt = 0; nt < 4; nt++)
                    mma_tf32(acc[mt][nt], af[mt], bf[nt]);
        }
        __syncthreads();
    }

    #pragma unroll
    for (int mt = 0; mt < 4; mt++) {
        #pragma unroll
        for (int nt = 0; nt < 4; nt++) {
            #pragma unroll
            for (int half = 0; half < 2; half++) {
                int gr = rowBase + warp_m * 64 + mt * 16 + (lane >> 2) + half * 8;
                int gc = colBase + warp_n * 32 + nt * 8 + (lane & 3) * 2;
                int bb = gr >> 11;
                size_t off = (size_t)gr * N + gc;
                float v0 = acc[mt][nt][half * 2 + 0];
                float v1 = acc[mt][nt][half * 2 + 1];
                if (MODE == 0) {
                    C[off] = v0; C[off + 1] = v1;
                } else if (MODE == 1) {
                    C[off]     = res[off]     + gate[bb * MODW + gc]     * v0;
                    C[off + 1] = res[off + 1] + gate[bb * MODW + gc + 1] * v1;
                } else if (MODE == 2) {
                    C[off]     = gelu_tanh(v0 + bias[gc]);
                    C[off + 1] = gelu_tanh(v1 + bias[gc + 1]);
                } else {
                    C[off]     = res[off]     + gate[bb * MODW + gc]     * (v0 + bias[gc]);
                    C[off + 1] = res[off + 1] + gate[bb * MODW + gc + 1] * (v1 + bias[gc + 1]);
                }
            }
        }
    }
}

// ---------------- 4) per-head rmsnorm + rope on q,k (in place in g_qkv) ----------------
__global__ void __launch_bounds__(1024)
rope_kernel(const float* __restrict__ qw, const float* __restrict__ kw,
            const float* __restrict__ cosb, const float* __restrict__ sinb) {
    __shared__ float sm[1024];
    __shared__ float part[32];
    int row = blockIdx.x;            // b*SEQ + s
    int s = row & (SEQ - 1);
    int t = threadIdx.x;             // 1024 threads
    int h = t >> 6, hd = t & 63;
    int wrp = t >> 5, lane = t & 31;
    float cs = cosb[s * HDIM + hd], sn = sinb[s * HDIM + hd];
    #pragma unroll
    for (int which = 0; which < 2; which++) {
        size_t base = ((size_t)row * 3 + which) * DMODEL;
        float v = g_qkv[base + t];
        float ss = v * v;
        #pragma unroll
        for (int off = 16; off; off >>= 1) ss += __shfl_xor_sync(0xffffffffu, ss, off);
        if (lane == 0) part[wrp] = ss;
        __syncthreads();
        float sumsq = part[2 * h] + part[2 * h + 1];
        float r = rsqrtf(sumsq * (1.0f / 64.0f) + 1e-6f);
        const float* ww = which ? kw : qw;
        float xn = v * r * ww[hd];
        sm[t] = xn;
        __syncthreads();
        float partner = sm[h * 64 + ((hd + 32) & 63)];
        float rot = (hd < 32) ? -partner : partner;
        g_qkv[base + t] = xn * cs + rot * sn;
        __syncthreads();
    }
}

// ---------------- 5) flash attention, tf32 tensor cores ----------------
// CTA: 64 q-rows (4 warps x m16), K-tiles of 64, cp.async double buffered K/V.
#define AKS 68   // K smem stride  (frag bank = 4*r0+q4 : conflict-free)
#define AVS 72   // V smem stride  (frag bank = 8*q4+r0 : conflict-free)
#define APS 68   // P smem stride
#define ATTN_SMEM ((2 * 64 * AKS + 2 * 64 * AVS + 64 * APS) * 4)

__global__ void __launch_bounds__(128)
attn_kernel() {
    extern __shared__ float smem[];
    float* ksm = smem;                        // [2][64*AKS]
    float* vsm = smem + 2 * 64 * AKS;         // [2][64*AVS]
    float* psm = vsm + 2 * 64 * AVS;          // [64*APS]

    const int qt = blockIdx.x, h = blockIdx.y, b = blockIdx.z;
    const int t = threadIdx.x;
    const int lane = t & 31, w = t >> 5;
    const int r0 = lane >> 2, q4 = lane & 3;

    const size_t kbase = ((size_t)(b * SEQ) * 3 + 1) * DMODEL + h * HDIM;
    const size_t vbase = kbase + DMODEL;
    const int qrow0 = b * SEQ + qt * 64 + w * 16;          // this warp's first q row
    const float* Qg = g_qkv + (size_t)qrow0 * 3 * DMODEL + h * HDIM;

    // fold softmax scale and log2(e) into Q
    const float lscale = 0.125f * 1.4426950408889634f;

    // Q A-fragments in registers (m16 x k64 = 8 k-steps)
    uint32_t qf[8][4];
    #pragma unroll
    for (int s = 0; s < 8; s++) {
        int kk = q4 + 8 * s;
        qf[s][0] = f2tf(Qg[(size_t)(r0    ) * 3072 + kk    ] * lscale);
        qf[s][1] = f2tf(Qg[(size_t)(r0 + 8) * 3072 + kk    ] * lscale);
        qf[s][2] = f2tf(Qg[(size_t)(r0    ) * 3072 + kk + 4] * lscale);
        qf[s][3] = f2tf(Qg[(size_t)(r0 + 8) * 3072 + kk + 4] * lscale);
    }

    float of[8][4];
    #pragma unroll
    for (int j = 0; j < 8; j++)
        #pragma unroll
        for (int f = 0; f < 4; f++) of[j][f] = 0.0f;
    float m0 = -1e30f, m1 = -1e30f, l0 = 0.0f, l1 = 0.0f;

    auto loadKV = [&](int k0, int buf) {
        #pragma unroll
        for (int i = 0; i < 8; i++) {
            int idx = t + i * 128;            // 0..1023
            int row = idx >> 4, quad = idx & 15;
            const float* srcK = g_qkv + kbase + (size_t)(k0 + row) * 3072 + quad * 4;
            uint32_t dstK = (uint32_t)__cvta_generic_to_shared(&ksm[buf * 64 * AKS + row * AKS + quad * 4]);
            asm volatile("cp.async.cg.shared.global [%0], [%1], 16;" :: "r"(dstK), "l"(srcK) : "memory");
            const float* srcV = g_qkv + vbase + (size_t)(k0 + row) * 3072 + quad * 4;
            uint32_t dstV = (uint32_t)__cvta_generic_to_shared(&vsm[buf * 64 * AVS + row * AVS + quad * 4]);
            asm volatile("cp.async.cg.shared.global [%0], [%1], 16;" :: "r"(dstV), "l"(srcV) : "memory");
        }
        asm volatile("cp.async.commit_group;" ::: "memory");
    };

    loadKV(0, 0);
    for (int kt = 0; kt < SEQ / 64; kt++) {
        if (kt + 1 < SEQ / 64) {
            loadKV((kt + 1) * 64, (kt + 1) & 1);
            asm volatile("cp.async.wait_group 1;" ::: "memory");
        } else {
            asm volatile("cp.async.wait_group 0;" ::: "memory");
        }
        __syncthreads();
        const float* kb = ksm + (kt & 1) * 64 * AKS;
        const float* vb = vsm + (kt & 1) * 64 * AVS;

        // S = Q K^T : 8 n-tiles x 8 k-steps
        float sf[8][4];
        #pragma unroll
        for (int j = 0; j < 8; j++)
            #pragma unroll
            for (int f = 0; f < 4; f++) sf[j][f] = 0.0f;
        #pragma unroll
        for (int s = 0; s < 8; s++) {
            #pragma unroll
            for (int j = 0; j < 8; j++) {
                uint32_t bf[2];
                bf[0] = f2tf(kb[(8 * j + r0) * AKS + q4 + 8 * s    ]);
                bf[1] = f2tf(kb[(8 * j + r0) * AKS + q4 + 8 * s + 4]);
                mma_tf32(sf[j], qf[s], bf);
            }
        }

        // online softmax on fragment layout (rows r0 and r0+8 of this warp's m16)
        float mx0 = -1e30f, mx1 = -1e30f;
        #pragma unroll
        for (int j = 0; j < 8; j++) {
            mx0 = fmaxf(mx0, fmaxf(sf[j][0], sf[j][1]));
            mx1 = fmaxf(mx1, fmaxf(sf[j][2], sf[j][3]));
        }
        #pragma unroll
        for (int off = 1; off < 4; off <<= 1) {
            mx0 = fmaxf(mx0, __shfl_xor_sync(0xffffffffu, mx0, off));
            mx1 = fmaxf(mx1, __shfl_xor_sync(0xffffffffu, mx1, off));
        }
        float nm0 = fmaxf(m0, mx0), nm1 = fmaxf(m1, mx1);
        float a0 = ex2(m0 - nm0), a1 = ex2(m1 - nm1);
        float s0 = 0.0f, s1 = 0.0f;
        float* prow0 = psm + (w * 16 + r0) * APS;
        float* prow1 = psm + (w * 16 + r0 + 8) * APS;
        #pragma unroll
        for (int j = 0; j < 8; j++) {
            float p00 = ex2(sf[j][0] - nm0);
            float p01 = ex2(sf[j][1] - nm0);
            float p10 = ex2(sf[j][2] - nm1);
            float p11 = ex2(sf[j][3] - nm1);
            s0 += p00 + p01;
            s1 += p10 + p11;
            float2 w0 = make_float2(__uint_as_float(f2tf(p00)), __uint_as_float(f2tf(p01)));
            float2 w1 = make_float2(__uint_as_float(f2tf(p10)), __uint_as_float(f2tf(p11)));
            *(float2*)(prow0 + 8 * j + 2 * q4) = w0;
            *(float2*)(prow1 + 8 * j + 2 * q4) = w1;
        }
        #pragma unroll
        for (int off = 1; off < 4; off <<= 1) {
            s0 += __shfl_xor_sync(0xffffffffu, s0, off);
            s1 += __shfl_xor_sync(0xffffffffu, s1, off);
        }
        m0 = nm0; m1 = nm1;
        l0 = l0 * a0 + s0;
        l1 = l1 * a1 + s1;
        #pragma unroll
        for (int j = 0; j < 8; j++) {
            of[j][0] *= a0; of[j][1] *= a0;
            of[j][2] *= a1; of[j][3] *= a1;
        }
        __syncwarp();

        // O += P V : P is m16 x k64 (A-frags from warp-private smem), V is k64 x n64
        #pragma unroll
        for (int s = 0; s < 8; s++) {
            uint32_t pf[4];
            int kk = q4 + 8 * s;
            pf[0] = __float_as_uint(prow0[kk    ]);
            pf[1] = __float_as_uint(prow1[kk    ]);
            pf[2] = __float_as_uint(prow0[kk + 4]);
            pf[3] = __float_as_uint(prow1[kk + 4]);
            #pragma unroll
            for (int j = 0; j < 8; j++) {
                uint32_t bf[2];
                bf[0] = f2tf(vb[(q4 + 8 * s    ) * AVS + r0 + 8 * j]);
                bf[1] = f2tf(vb[(q4 + 8 * s + 4) * AVS + r0 + 8 * j]);
                mma_tf32(of[j], pf, bf);
            }
        }
        __syncthreads();   // all warps done with this K/V buffer before cp.async reuse
    }

    float inv0 = 1.0f / l0, inv1 = 1.0f / l1;
    #pragma unroll
    for (int j = 0; j < 8; j++) {
        size_t base0 = (size_t)(qrow0 + r0    ) * DMODEL + h * HDIM + 8 * j + 2 * q4;
        size_t base1 = (size_t)(qrow0 + r0 + 8) * DMODEL + h * HDIM + 8 * j + 2 * q4;
        g_attn[base0]     = of[j][0] * inv0;
        g_attn[base0 + 1] = of[j][1] * inv0;
        g_attn[base1]     = of[j][2] * inv1;
        g_attn[base1 + 1] = of[j][3] * inv1;
    }
}

// ---------------- launch ----------------
extern "C" void kernel_launch(void* const* d_in, const int* in_sizes, int n_in,
                              void* d_out, int out_size) {
    const float* x       = (const float*)d_in[0];
    const float* cosb    = (const float*)d_in[1];
    const float* sinb    = (const float*)d_in[2];
    const float* c       = (const float*)d_in[3];
    const float* norm1_w = (const float*)d_in[4];
    const float* Wqkv    = (const float*)d_in[5];
    const float* Wout    = (const float*)d_in[6];
    const float* q_norm_w = (const float*)d_in[7];
    const float* k_norm_w = (const float*)d_in[8];
    const float* norm2_w = (const float*)d_in[9];
    const float* W1      = (const float*)d_in[10];
    const float* b1      = (const float*)d_in[11];
    const float* W2      = (const float*)d_in[12];
    const float* b2      = (const float*)d_in[13];
    const float* ada_W   = (const float*)d_in[14];
    const float* ada_b   = (const float*)d_in[15];
    float* out = (float*)d_out;

    float *p_mod, *p_xn, *p_qkv, *p_attn, *p_x2, *p_h;
    cudaGetSymbolAddress((void**)&p_mod, g_mod);
    cudaGetSymbolAddress((void**)&p_xn, g_xn);
    cudaGetSymbolAddress((void**)&p_qkv, g_qkv);
    cudaGetSymbolAddress((void**)&p_attn, g_attn);
    cudaGetSymbolAddress((void**)&p_x2, g_x2);
    cudaGetSymbolAddress((void**)&p_h, g_h);

    cudaFuncSetAttribute(attn_kernel, cudaFuncAttributeMaxDynamicSharedMemorySize, ATTN_SMEM);

    // 1) adaLN modulation vectors
    mod_kernel<<<dim3(MODW / 256, BATCH), 256>>>(c, ada_W, ada_b);
    // 2) LN1 + modulate
    ln_mod_kernel<<<NROWS, 256>>>(x, norm1_w, 0, 1024, p_xn);
    // 3) qkv = xn @ Wqkv   (TF32 tensor cores)
    mma_gemm<0><<<dim3(3 * DMODEL / 128, NROWS / 128), 256>>>(
        p_xn, Wqkv, p_qkv, NROWS, 3 * DMODEL, DMODEL, nullptr, nullptr, nullptr);
    // 4) rmsnorm + rope on q,k (in place)
    rope_kernel<<<NROWS, 1024>>>(q_norm_w, k_norm_w, cosb, sinb);
    // 5) attention (TF32 tensor cores)
    attn_kernel<<<dim3(SEQ / 64, NHEADS, BATCH), 128, ATTN_SMEM>>>();
    // 6) x2 = x + g_msa * (attn @ Wout)
    mma_gemm<1><<<dim3(DMODEL / 128, NROWS / 128), 256>>>(
        p_attn, Wout, p_x2, NROWS, DMODEL, DMODEL, x, nullptr, p_mod + 2 * 1024);
    // 7) LN2 + modulate
    ln_mod_kernel<<<NROWS, 256>>>(p_x2, norm2_w, 3 * 1024, 4 * 1024, p_xn);
    // 8) h = gelu(xn @ W1 + b1)
    mma_gemm<2><<<dim3(DFF / 128, NROWS / 128), 256>>>(
        p_xn, W1, p_h, NROWS, DFF, DMODEL, nullptr, b1, nullptr);
    // 9) out = x2 + g_mlp * (h @ W2 + b2)
    mma_gemm<3><<<dim3(DMODEL / 128, NROWS / 128), 256>>>(
        p_h, W2, out, NROWS, DMODEL, DFF, p_x2, b2, p_mod + 5 * 1024);
}

// round 7
// speedup vs baseline: 3.0778x; 1.0743x over previous
#include <cuda_runtime.h>
#include <math.h>
#include <stdint.h>

#define DMODEL 1024
#define SEQ    2048
#define BATCH  4
#define NHEADS 16
#define HDIM   64
#define DFF    4096
#define NROWS  8192      // BATCH*SEQ
#define MODW   6144

// ---------------- scratch (static device arrays; no allocation) ----------------
__device__ float g_mod[BATCH * MODW];
__device__ float g_xn[(size_t)NROWS * DMODEL];
__device__ float g_qkv[(size_t)NROWS * 3 * DMODEL];
__device__ float g_attn[(size_t)NROWS * DMODEL];
__device__ float g_x2[(size_t)NROWS * DMODEL];
__device__ float g_h[(size_t)NROWS * DFF];
// tf32-pre-rounded weight copies
__device__ float g_wqkv[(size_t)DMODEL * 3 * DMODEL];
__device__ float g_wout[(size_t)DMODEL * DMODEL];
__device__ float g_w1[(size_t)DMODEL * DFF];
__device__ float g_w2[(size_t)DFF * DMODEL];

// ---------------- helpers ----------------
__device__ __forceinline__ float gelu_tanh(float x) {
    float x3 = x * x * x;
    float u = 0.7978845608028654f * (x + 0.044715f * x3);
    return 0.5f * x * (1.0f + tanhf(u));
}

__device__ __forceinline__ uint32_t f2tf(float f) {
    uint32_t u;
    asm("cvt.rna.tf32.f32 %0, %1;" : "=r"(u) : "f"(f));
    return u;
}
__device__ __forceinline__ float rtf(float f) { return __uint_as_float(f2tf(f)); }

__device__ __forceinline__ float ex2(float x) {
    float r;
    asm("ex2.approx.ftz.f32 %0, %1;" : "=f"(r) : "f"(x));
    return r;
}

__device__ __forceinline__ void mma_tf32(float c[4], const uint32_t a[4], const uint32_t b[2]) {
    asm volatile(
        "mma.sync.aligned.m16n8k8.row.col.f32.tf32.tf32.f32 "
        "{%0,%1,%2,%3}, {%4,%5,%6,%7}, {%8,%9}, {%0,%1,%2,%3};\n"
        : "+f"(c[0]), "+f"(c[1]), "+f"(c[2]), "+f"(c[3])
        : "r"(a[0]), "r"(a[1]), "r"(a[2]), "r"(a[3]), "r"(b[0]), "r"(b[1]));
}

__device__ __forceinline__ void blockReduce2(float& a, float& b) {
    #pragma unroll
    for (int off = 16; off; off >>= 1) {
        a += __shfl_xor_sync(0xffffffffu, a, off);
        b += __shfl_xor_sync(0xffffffffu, b, off);
    }
    __shared__ float sa[8], sb[8];
    int w = threadIdx.x >> 5, l = threadIdx.x & 31;
    if (l == 0) { sa[w] = a; sb[w] = b; }
    __syncthreads();
    if (w == 0) {
        a = (l < 8) ? sa[l] : 0.0f;
        b = (l < 8) ? sb[l] : 0.0f;
        #pragma unroll
        for (int off = 4; off; off >>= 1) {
            a += __shfl_xor_sync(0xffffffffu, a, off);
            b += __shfl_xor_sync(0xffffffffu, b, off);
        }
        if (l == 0) { sa[0] = a; sb[0] = b; }
    }
    __syncthreads();
    a = sa[0]; b = sb[0];
}

// ---------------- 0) tf32 pre-rounding of weights ----------------
__global__ void round_kernel(const float* __restrict__ in, float* __restrict__ out) {
    int i = blockIdx.x * 256 + threadIdx.x;
    float4 v = ((const float4*)in)[i];
    v.x = rtf(v.x); v.y = rtf(v.y); v.z = rtf(v.z); v.w = rtf(v.w);
    ((float4*)out)[i] = v;
}

// ---------------- 1) mod = c @ ada_W + ada_b ----------------
__global__ void mod_kernel(const float* __restrict__ c, const float* __restrict__ W,
                           const float* __restrict__ bias) {
    __shared__ float cs[1024];
    int b = blockIdx.y;
    int col = blockIdx.x * 256 + threadIdx.x;
    for (int i = threadIdx.x; i < 1024; i += 256) cs[i] = c[b * 1024 + i];
    __syncthreads();
    float acc = 0.0f;
    #pragma unroll 4
    for (int k = 0; k < 1024; k++) acc += cs[k] * W[(size_t)k * MODW + col];
    g_mod[b * MODW + col] = acc + bias[col];
}

// ---------------- 2) layernorm + modulate (output tf32-rounded) ----------------
__global__ void ln_mod_kernel(const float* __restrict__ X, const float* __restrict__ w,
                              int shOff, int scOff, float* __restrict__ out) {
    int row = blockIdx.x;
    int b = row >> 11;
    const float4* xr = (const float4*)(X + (size_t)row * DMODEL);
    float4 v = xr[threadIdx.x];
    float s = v.x + v.y + v.z + v.w;
    float ss = v.x * v.x + v.y * v.y + v.z * v.z + v.w * v.w;
    blockReduce2(s, ss);
    float mu = s * (1.0f / 1024.0f);
    float var = ss * (1.0f / 1024.0f) - mu * mu;
    float r = rsqrtf(var + 1e-5f);
    int d = threadIdx.x * 4;
    const float* mb = g_mod + b * MODW;
    float4 o;
    o.x = rtf((v.x - mu) * r * w[d + 0] * (1.0f + mb[scOff + d + 0]) + mb[shOff + d + 0]);
    o.y = rtf((v.y - mu) * r * w[d + 1] * (1.0f + mb[scOff + d + 1]) + mb[shOff + d + 1]);
    o.z = rtf((v.z - mu) * r * w[d + 2] * (1.0f + mb[scOff + d + 2]) + mb[shOff + d + 2]);
    o.w = rtf((v.w - mu) * r * w[d + 3] * (1.0f + mb[scOff + d + 3]) + mb[shOff + d + 3]);
    ((float4*)(out + (size_t)row * DMODEL))[threadIdx.x] = o;
}

// ---------------- 3) TF32 tensor-core GEMM (operands pre-rounded, no cvt in loop) ----
// MODE 0: C = acc                         (rounded: feeds rope/attention via qkv)
// MODE 1: C = res + gate * acc            (full fp32: residual stream)
// MODE 2: C = round(gelu(acc + bias))     (feeds W2 GEMM)
// MODE 3: C = res + gate * (acc + bias)   (full fp32: final output)
#define AS_STRIDE 20
#define BS_STRIDE 136

template<int MODE>
__global__ void __launch_bounds__(256, 2)
mma_gemm(const float* __restrict__ A, const float* __restrict__ B, float* __restrict__ C,
         int M, int N, int K,
         const float* __restrict__ res, const float* __restrict__ bias,
         const float* __restrict__ gate) {
    __shared__ float As[2][128 * AS_STRIDE];
    __shared__ float Bs[2][16 * BS_STRIDE];
    const int t = threadIdx.x;
    const int lane = t & 31, wid = t >> 5;
    const int warp_m = wid & 1, warp_n = wid >> 1;   // 2 x 4 warp grid
    const int rowBase = blockIdx.y * 128, colBase = blockIdx.x * 128;

    const int nk = K >> 4;

    float acc[4][4][4];
    #pragma unroll
    for (int mt = 0; mt < 4; mt++)
        #pragma unroll
        for (int nt = 0; nt < 4; nt++)
            #pragma unroll
            for (int f = 0; f < 4; f++) acc[mt][nt][f] = 0.0f;

    auto load_stage = [&](int kt, int buf) {
        #pragma unroll
        for (int i = 0; i < 2; i++) {
            int idx = t + i * 256;           // 0..511
            int r = idx >> 2, q = idx & 3;   // 128 rows x 4 k-quads
            const float* src = A + (size_t)(rowBase + r) * K + kt * 16 + q * 4;
            uint32_t dst = (uint32_t)__cvta_generic_to_shared(&As[buf][r * AS_STRIDE + q * 4]);
            asm volatile("cp.async.cg.shared.global [%0], [%1], 16;" :: "r"(dst), "l"(src) : "memory");
        }
        #pragma unroll
        for (int i = 0; i < 2; i++) {
            int idx = t + i * 256;           // 0..511
            int k = idx >> 5, cq = idx & 31; // 16 k-rows x 32 col-quads
            const float* src = B + (size_t)(kt * 16 + k) * N + colBase + cq * 4;
            uint32_t dst = (uint32_t)__cvta_generic_to_shared(&Bs[buf][k * BS_STRIDE + cq * 4]);
            asm volatile("cp.async.cg.shared.global [%0], [%1], 16;" :: "r"(dst), "l"(src) : "memory");
        }
        asm volatile("cp.async.commit_group;" ::: "memory");
    };

    load_stage(0, 0);
    for (int kt = 0; kt < nk; kt++) {
        if (kt + 1 < nk) {
            load_stage(kt + 1, (kt + 1) & 1);
            asm volatile("cp.async.wait_group 1;" ::: "memory");
        } else {
            asm volatile("cp.async.wait_group 0;" ::: "memory");
        }
        __syncthreads();
        const float* as = As[kt & 1];
        const float* bs = Bs[kt & 1];
        #pragma unroll
        for (int ks = 0; ks < 2; ks++) {
            const int k0 = ks * 8;
            uint32_t af[4][4], bf[4][2];
            const int kk = k0 + (lane & 3);
            #pragma unroll
            for (int mt = 0; mt < 4; mt++) {
                int m0 = warp_m * 64 + mt * 16 + (lane >> 2);
                af[mt][0] = __float_as_uint(as[(m0    ) * AS_STRIDE + kk    ]);
                af[mt][1] = __float_as_uint(as[(m0 + 8) * AS_STRIDE + kk    ]);
                af[mt][2] = __float_as_uint(as[(m0    ) * AS_STRIDE + kk + 4]);
                af[mt][3] = __float_as_uint(as[(m0 + 8) * AS_STRIDE + kk + 4]);
            }
            #pragma unroll
            for (int nt = 0; nt < 4; nt++) {
                int n0 = warp_n * 32 + nt * 8 + (lane >> 2);
                bf[nt][0] = __float_as_uint(bs[(kk    ) * BS_STRIDE + n0]);
                bf[nt][1] = __float_as_uint(bs[(kk + 4) * BS_STRIDE + n0]);
            }
            #pragma unroll
            for (int mt = 0; mt < 4; mt++)
                #pragma unroll
                for (int nt = 0; nt < 4; nt++)
                    mma_tf32(acc[mt][nt], af[mt], bf[nt]);
        }
        __syncthreads();
    }

    #pragma unroll
    for (int mt = 0; mt < 4; mt++) {
        #pragma unroll
        for (int nt = 0; nt < 4; nt++) {
            #pragma unroll
            for (int half = 0; half < 2; half++) {
                int gr = rowBase + warp_m * 64 + mt * 16 + (lane >> 2) + half * 8;
                int gc = colBase + warp_n * 32 + nt * 8 + (lane & 3) * 2;
                int bb = gr >> 11;
                size_t off = (size_t)gr * N + gc;
                float v0 = acc[mt][nt][half * 2 + 0];
                float v1 = acc[mt][nt][half * 2 + 1];
                if (MODE == 0) {
                    C[off] = v0; C[off + 1] = v1;
                } else if (MODE == 1) {
                    C[off]     = res[off]     + gate[bb * MODW + gc]     * v0;
                    C[off + 1] = res[off + 1] + gate[bb * MODW + gc + 1] * v1;
                } else if (MODE == 2) {
                    C[off]     = rtf(gelu_tanh(v0 + bias[gc]));
                    C[off + 1] = rtf(gelu_tanh(v1 + bias[gc + 1]));
                } else {
                    C[off]     = res[off]     + gate[bb * MODW + gc]     * (v0 + bias[gc]);
                    C[off + 1] = res[off + 1] + gate[bb * MODW + gc + 1] * (v1 + bias[gc + 1]);
                }
            }
        }
    }
}

// ---------------- 4) rmsnorm + rope on q,k + rounding of q,k,v (in place) ----------
// q additionally scaled by 0.125*log2(e) (softmax scale folded in for attention).
__global__ void __launch_bounds__(1024)
rope_kernel(const float* __restrict__ qw, const float* __restrict__ kw,
            const float* __restrict__ cosb, const float* __restrict__ sinb) {
    __shared__ float sm[1024];
    __shared__ float part[32];
    int row = blockIdx.x;            // b*SEQ + s
    int s = row & (SEQ - 1);
    int t = threadIdx.x;             // 1024 threads
    int h = t >> 6, hd = t & 63;
    int wrp = t >> 5, lane = t & 31;
    float cs = cosb[s * HDIM + hd], sn = sinb[s * HDIM + hd];
    const float lscale = 0.125f * 1.4426950408889634f;
    #pragma unroll
    for (int which = 0; which < 2; which++) {
        size_t base = ((size_t)row * 3 + which) * DMODEL;
        float v = g_qkv[base + t];
        float ss = v * v;
        #pragma unroll
        for (int off = 16; off; off >>= 1) ss += __shfl_xor_sync(0xffffffffu, ss, off);
        if (lane == 0) part[wrp] = ss;
        __syncthreads();
        float sumsq = part[2 * h] + part[2 * h + 1];
        float r = rsqrtf(sumsq * (1.0f / 64.0f) + 1e-6f);
        const float* ww = which ? kw : qw;
        float xn = v * r * ww[hd];
        sm[t] = xn;
        __syncthreads();
        float partner = sm[h * 64 + ((hd + 32) & 63)];
        float rot = (hd < 32) ? -partner : partner;
        float val = xn * cs + rot * sn;
        if (which == 0) val *= lscale;
        g_qkv[base + t] = rtf(val);
        __syncthreads();
    }
    // v: round only
    size_t vb = ((size_t)row * 3 + 2) * DMODEL;
    g_qkv[vb + t] = rtf(g_qkv[vb + t]);
}

// ---------------- 5) flash attention, tf32 tensor cores (operands pre-rounded) -----
#define AKS 68   // K smem stride
#define AVS 72   // V smem stride
#define APS 68   // P smem stride
#define ATTN_SMEM ((2 * 64 * AKS + 2 * 64 * AVS + 64 * APS) * 4)

__global__ void __launch_bounds__(128)
attn_kernel() {
    extern __shared__ float smem[];
    float* ksm = smem;                        // [2][64*AKS]
    float* vsm = smem + 2 * 64 * AKS;         // [2][64*AVS]
    float* psm = vsm + 2 * 64 * AVS;          // [64*APS]

    const int qt = blockIdx.x, h = blockIdx.y, b = blockIdx.z;
    const int t = threadIdx.x;
    const int lane = t & 31, w = t >> 5;
    const int r0 = lane >> 2, q4 = lane & 3;

    const size_t kbase = ((size_t)(b * SEQ) * 3 + 1) * DMODEL + h * HDIM;
    const size_t vbase = kbase + DMODEL;
    const int qrow0 = b * SEQ + qt * 64 + w * 16;          // this warp's first q row
    const float* Qg = g_qkv + (size_t)qrow0 * 3 * DMODEL + h * HDIM;

    // Q A-fragments (already scaled + tf32-rounded by rope)
    uint32_t qf[8][4];
    #pragma unroll
    for (int s = 0; s < 8; s++) {
        int kk = q4 + 8 * s;
        qf[s][0] = __float_as_uint(Qg[(size_t)(r0    ) * 3072 + kk    ]);
        qf[s][1] = __float_as_uint(Qg[(size_t)(r0 + 8) * 3072 + kk    ]);
        qf[s][2] = __float_as_uint(Qg[(size_t)(r0    ) * 3072 + kk + 4]);
        qf[s][3] = __float_as_uint(Qg[(size_t)(r0 + 8) * 3072 + kk + 4]);
    }

    float of[8][4];
    #pragma unroll
    for (int j = 0; j < 8; j++)
        #pragma unroll
        for (int f = 0; f < 4; f++) of[j][f] = 0.0f;
    float m0 = -1e30f, m1 = -1e30f, l0 = 0.0f, l1 = 0.0f;

    auto loadKV = [&](int k0, int buf) {
        #pragma unroll
        for (int i = 0; i < 8; i++) {
            int idx = t + i * 128;            // 0..1023
            int row = idx >> 4, quad = idx & 15;
            const float* srcK = g_qkv + kbase + (size_t)(k0 + row) * 3072 + quad * 4;
            uint32_t dstK = (uint32_t)__cvta_generic_to_shared(&ksm[buf * 64 * AKS + row * AKS + quad * 4]);
            asm volatile("cp.async.cg.shared.global [%0], [%1], 16;" :: "r"(dstK), "l"(srcK) : "memory");
            const float* srcV = g_qkv + vbase + (size_t)(k0 + row) * 3072 + quad * 4;
            uint32_t dstV = (uint32_t)__cvta_generic_to_shared(&vsm[buf * 64 * AVS + row * AVS + quad * 4]);
            asm volatile("cp.async.cg.shared.global [%0], [%1], 16;" :: "r"(dstV), "l"(srcV) : "memory");
        }
        asm volatile("cp.async.commit_group;" ::: "memory");
    };

    loadKV(0, 0);
    for (int kt = 0; kt < SEQ / 64; kt++) {
        if (kt + 1 < SEQ / 64) {
            loadKV((kt + 1) * 64, (kt + 1) & 1);
            asm volatile("cp.async.wait_group 1;" ::: "memory");
        } else {
            asm volatile("cp.async.wait_group 0;" ::: "memory");
        }
        __syncthreads();
        const float* kb = ksm + (kt & 1) * 64 * AKS;
        const float* vb = vsm + (kt & 1) * 64 * AVS;

        // S = Q K^T
        float sf[8][4];
        #pragma unroll
        for (int j = 0; j < 8; j++)
            #pragma unroll
            for (int f = 0; f < 4; f++) sf[j][f] = 0.0f;
        #pragma unroll
        for (int s = 0; s < 8; s++) {
            #pragma unroll
            for (int j = 0; j < 8; j++) {
                uint32_t bf[2];
                bf[0] = __float_as_uint(kb[(8 * j + r0) * AKS + q4 + 8 * s    ]);
                bf[1] = __float_as_uint(kb[(8 * j + r0) * AKS + q4 + 8 * s + 4]);
                mma_tf32(sf[j], qf[s], bf);
            }
        }

        // online softmax on fragment layout
        float mx0 = -1e30f, mx1 = -1e30f;
        #pragma unroll
        for (int j = 0; j < 8; j++) {
            mx0 = fmaxf(mx0, fmaxf(sf[j][0], sf[j][1]));
            mx1 = fmaxf(mx1, fmaxf(sf[j][2], sf[j][3]));
        }
        #pragma unroll
        for (int off = 1; off < 4; off <<= 1) {
            mx0 = fmaxf(mx0, __shfl_xor_sync(0xffffffffu, mx0, off));
            mx1 = fmaxf(mx1, __shfl_xor_sync(0xffffffffu, mx1, off));
        }
        float nm0 = fmaxf(m0, mx0), nm1 = fmaxf(m1, mx1);
        float a0 = ex2(m0 - nm0), a1 = ex2(m1 - nm1);
        float s0 = 0.0f, s1 = 0.0f;
        float* prow0 = psm + (w * 16 + r0) * APS;
        float* prow1 = psm + (w * 16 + r0 + 8) * APS;
        #pragma unroll
        for (int j = 0; j < 8; j++) {
            float p00 = ex2(sf[j][0] - nm0);
            float p01 = ex2(sf[j][1] - nm0);
            float p10 = ex2(sf[j][2] - nm1);
            float p11 = ex2(sf[j][3] - nm1);
            s0 += p00 + p01;
            s1 += p10 + p11;
            float2 w0 = make_float2(rtf(p00), rtf(p01));
            float2 w1 = make_float2(rtf(p10), rtf(p11));
            *(float2*)(prow0 + 8 * j + 2 * q4) = w0;
            *(float2*)(prow1 + 8 * j + 2 * q4) = w1;
        }
        #pragma unroll
        for (int off = 1; off < 4; off <<= 1) {
            s0 += __shfl_xor_sync(0xffffffffu, s0, off);
            s1 += __shfl_xor_sync(0xffffffffu, s1, off);
        }
        m0 = nm0; m1 = nm1;
        l0 = l0 * a0 + s0;
        l1 = l1 * a1 + s1;
        #pragma unroll
        for (int j = 0; j < 8; j++) {
            of[j][0] *= a0; of[j][1] *= a0;
            of[j][2] *= a1; of[j][3] *= a1;
        }
        __syncwarp();

        // O += P V
        #pragma unroll
        for (int s = 0; s < 8; s++) {
            uint32_t pf[4];
            int kk = q4 + 8 * s;
            pf[0] = __float_as_uint(prow0[kk    ]);
            pf[1] = __float_as_uint(prow1[kk    ]);
            pf[2] = __float_as_uint(prow0[kk + 4]);
            pf[3] = __float_as_uint(prow1[kk + 4]);
            #pragma unroll
            for (int j = 0; j < 8; j++) {
                uint32_t bf[2];
                bf[0] = __float_as_uint(vb[(q4 + 8 * s    ) * AVS + r0 + 8 * j]);
                bf[1] = __float_as_uint(vb[(q4 + 8 * s + 4) * AVS + r0 + 8 * j]);
                mma_tf32(of[j], pf, bf);
            }
        }
        __syncthreads();   // all warps done with this K/V buffer before cp.async reuse
    }

    float inv0 = 1.0f / l0, inv1 = 1.0f / l1;
    #pragma unroll
    for (int j = 0; j < 8; j++) {
        size_t base0 = (size_t)(qrow0 + r0    ) * DMODEL + h * HDIM + 8 * j + 2 * q4;
        size_t base1 = (size_t)(qrow0 + r0 + 8) * DMODEL + h * HDIM + 8 * j + 2 * q4;
        g_attn[base0]     = rtf(of[j][0] * inv0);
        g_attn[base0 + 1] = rtf(of[j][1] * inv0);
        g_attn[base1]     = rtf(of[j][2] * inv1);
        g_attn[base1 + 1] = rtf(of[j][3] * inv1);
    }
}

// ---------------- launch ----------------
extern "C" void kernel_launch(void* const* d_in, const int* in_sizes, int n_in,
                              void* d_out, int out_size) {
    const float* x       = (const float*)d_in[0];
    const float* cosb    = (const float*)d_in[1];
    const float* sinb    = (const float*)d_in[2];
    const float* c       = (const float*)d_in[3];
    const float* norm1_w = (const float*)d_in[4];
    const float* Wqkv    = (const float*)d_in[5];
    const float* Wout    = (const float*)d_in[6];
    const float* q_norm_w = (const float*)d_in[7];
    const float* k_norm_w = (const float*)d_in[8];
    const float* norm2_w = (const float*)d_in[9];
    const float* W1      = (const float*)d_in[10];
    const float* b1      = (const float*)d_in[11];
    const float* W2      = (const float*)d_in[12];
    const float* b2      = (const float*)d_in[13];
    const float* ada_W   = (const float*)d_in[14];
    const float* ada_b   = (const float*)d_in[15];
    float* out = (float*)d_out;

    float *p_mod, *p_xn, *p_qkv, *p_attn, *p_x2, *p_h;
    float *p_wqkv, *p_wout, *p_w1, *p_w2;
    cudaGetSymbolAddress((void**)&p_mod, g_mod);
    cudaGetSymbolAddress((void**)&p_xn, g_xn);
    cudaGetSymbolAddress((void**)&p_qkv, g_qkv);
    cudaGetSymbolAddress((void**)&p_attn, g_attn);
    cudaGetSymbolAddress((void**)&p_x2, g_x2);
    cudaGetSymbolAddress((void**)&p_h, g_h);
    cudaGetSymbolAddress((void**)&p_wqkv, g_wqkv);
    cudaGetSymbolAddress((void**)&p_wout, g_wout);
    cudaGetSymbolAddress((void**)&p_w1, g_w1);
    cudaGetSymbolAddress((void**)&p_w2, g_w2);

    cudaFuncSetAttribute(attn_kernel, cudaFuncAttributeMaxDynamicSharedMemorySize, ATTN_SMEM);

    // 0) pre-round weights to tf32 (once per launch; graph replays include it)
    round_kernel<<<(3 * DMODEL * DMODEL) / 1024, 256>>>(Wqkv, p_wqkv);
    round_kernel<<<(DMODEL * DMODEL) / 1024, 256>>>(Wout, p_wout);
    round_kernel<<<(DMODEL * DFF) / 1024, 256>>>(W1, p_w1);
    round_kernel<<<(DFF * DMODEL) / 1024, 256>>>(W2, p_w2);
    // 1) adaLN modulation vectors
    mod_kernel<<<dim3(MODW / 256, BATCH), 256>>>(c, ada_W, ada_b);
    // 2) LN1 + modulate
    ln_mod_kernel<<<NROWS, 256>>>(x, norm1_w, 0, 1024, p_xn);
    // 3) qkv = xn @ Wqkv
    mma_gemm<0><<<dim3(3 * DMODEL / 128, NROWS / 128), 256>>>(
        p_xn, p_wqkv, p_qkv, NROWS, 3 * DMODEL, DMODEL, nullptr, nullptr, nullptr);
    // 4) rmsnorm + rope + tf32 rounding on q,k,v (in place)
    rope_kernel<<<NROWS, 1024>>>(q_norm_w, k_norm_w, cosb, sinb);
    // 5) attention
    attn_kernel<<<dim3(SEQ / 64, NHEADS, BATCH), 128, ATTN_SMEM>>>();
    // 6) x2 = x + g_msa * (attn @ Wout)
    mma_gemm<1><<<dim3(DMODEL / 128, NROWS / 128), 256>>>(
        p_attn, p_wout, p_x2, NROWS, DMODEL, DMODEL, x, nullptr, p_mod + 2 * 1024);
    // 7) LN2 + modulate
    ln_mod_kernel<<<NROWS, 256>>>(p_x2, norm2_w, 3 * 1024, 4 * 1024, p_xn);
    // 8) h = gelu(xn @ W1 + b1)
    mma_gemm<2><<<dim3(DFF / 128, NROWS / 128), 256>>>(
        p_xn, p_w1, p_h, NROWS, DFF, DMODEL, nullptr, b1, nullptr);
    // 9) out = x2 + g_mlp * (h @ W2 + b2)
    mma_gemm<3><<<dim3(DMODEL / 128, NROWS / 128), 256>>>(
        p_h, p_w2, out, NROWS, DMODEL, DFF, p_x2, b2, p_mod + 5 * 1024);
}

// round 8
// speedup vs baseline: 6.0824x; 1.9762x over previous
#include <cuda_runtime.h>
#include <cuda_fp16.h>
#include <math.h>
#include <stdint.h>

#define DMODEL 1024
#define SEQ    2048
#define BATCH  4
#define NHEADS 16
#define HDIM   64
#define DFF    4096
#define NROWS  8192
#define MODW   6144

// ---------------- scratch ----------------
__device__ float  g_mod[BATCH * MODW];
__device__ float  g_x2[(size_t)NROWS * DMODEL];
__device__ __half g_xnh[(size_t)NROWS * DMODEL];
__device__ __half g_qkvh[(size_t)NROWS * 3 * DMODEL];
__device__ __half g_attnh[(size_t)NROWS * DMODEL];
__device__ __half g_hh[(size_t)NROWS * DFF];
__device__ __half g_wqkvh[(size_t)DMODEL * 3 * DMODEL];
__device__ __half g_wouth[(size_t)DMODEL * DMODEL];
__device__ __half g_w1h[(size_t)DMODEL * DFF];
__device__ __half g_w2h[(size_t)DFF * DMODEL];

// ---------------- helpers ----------------
__device__ __forceinline__ float gelu_tanh(float x) {
    float x3 = x * x * x;
    float u = 0.7978845608028654f * (x + 0.044715f * x3);
    return 0.5f * x * (1.0f + tanhf(u));
}
__device__ __forceinline__ float ex2(float x) {
    float r; asm("ex2.approx.ftz.f32 %0, %1;" : "=f"(r) : "f"(x)); return r;
}
__device__ __forceinline__ uint32_t h2u(__half2 h) { return *(uint32_t*)&h; }

__device__ __forceinline__ void mma_f16(float c[4], const uint32_t a[4], const uint32_t b[2]) {
    asm volatile(
        "mma.sync.aligned.m16n8k16.row.col.f32.f16.f16.f32 "
        "{%0,%1,%2,%3}, {%4,%5,%6,%7}, {%8,%9}, {%0,%1,%2,%3};\n"
        : "+f"(c[0]), "+f"(c[1]), "+f"(c[2]), "+f"(c[3])
        : "r"(a[0]), "r"(a[1]), "r"(a[2]), "r"(a[3]), "r"(b[0]), "r"(b[1]));
}
__device__ __forceinline__ void ldsm_x4(uint32_t& r0, uint32_t& r1, uint32_t& r2, uint32_t& r3, uint32_t addr) {
    asm volatile("ldmatrix.sync.aligned.m8n8.x4.shared.b16 {%0,%1,%2,%3}, [%4];"
                 : "=r"(r0), "=r"(r1), "=r"(r2), "=r"(r3) : "r"(addr));
}
__device__ __forceinline__ void ldsm_x4_t(uint32_t& r0, uint32_t& r1, uint32_t& r2, uint32_t& r3, uint32_t addr) {
    asm volatile("ldmatrix.sync.aligned.m8n8.x4.trans.shared.b16 {%0,%1,%2,%3}, [%4];"
                 : "=r"(r0), "=r"(r1), "=r"(r2), "=r"(r3) : "r"(addr));
}
__device__ __forceinline__ void cpa16(uint32_t dst, const void* src) {
    asm volatile("cp.async.cg.shared.global [%0], [%1], 16;" :: "r"(dst), "l"(src) : "memory");
}

__device__ __forceinline__ void blockReduce2(float& a, float& b) {
    #pragma unroll
    for (int off = 16; off; off >>= 1) {
        a += __shfl_xor_sync(0xffffffffu, a, off);
        b += __shfl_xor_sync(0xffffffffu, b, off);
    }
    __shared__ float sa[8], sb[8];
    int w = threadIdx.x >> 5, l = threadIdx.x & 31;
    if (l == 0) { sa[w] = a; sb[w] = b; }
    __syncthreads();
    if (w == 0) {
        a = (l < 8) ? sa[l] : 0.0f;
        b = (l < 8) ? sb[l] : 0.0f;
        #pragma unroll
        for (int off = 4; off; off >>= 1) {
            a += __shfl_xor_sync(0xffffffffu, a, off);
            b += __shfl_xor_sync(0xffffffffu, b, off);
        }
        if (l == 0) { sa[0] = a; sb[0] = b; }
    }
    __syncthreads();
    a = sa[0]; b = sb[0];
}

// ---------------- 0) fp32 -> fp16 weight conversion ----------------
__global__ void cvth_kernel(const float* __restrict__ in, __half* __restrict__ out) {
    int i = blockIdx.x * 256 + threadIdx.x;
    float4 v = ((const float4*)in)[i];
    __half2 lo = __floats2half2_rn(v.x, v.y);
    __half2 hi = __floats2half2_rn(v.z, v.w);
    ((uint2*)out)[i] = make_uint2(h2u(lo), h2u(hi));
}

// ---------------- 1) mod = c @ ada_W + ada_b ----------------
__global__ void mod_kernel(const float* __restrict__ c, const float* __restrict__ W,
                           const float* __restrict__ bias) {
    __shared__ float cs[1024];
    int b = blockIdx.y;
    int col = blockIdx.x * 256 + threadIdx.x;
    for (int i = threadIdx.x; i < 1024; i += 256) cs[i] = c[b * 1024 + i];
    __syncthreads();
    float acc = 0.0f;
    #pragma unroll 4
    for (int k = 0; k < 1024; k++) acc += cs[k] * W[(size_t)k * MODW + col];
    g_mod[b * MODW + col] = acc + bias[col];
}

// ---------------- 2) layernorm + modulate -> half ----------------
__global__ void ln_mod_kernel(const float* __restrict__ X, const float* __restrict__ w,
                              int shOff, int scOff, __half* __restrict__ out) {
    int row = blockIdx.x;
    int b = row >> 11;
    const float4* xr = (const float4*)(X + (size_t)row * DMODEL);
    float4 v = xr[threadIdx.x];
    float s = v.x + v.y + v.z + v.w;
    float ss = v.x * v.x + v.y * v.y + v.z * v.z + v.w * v.w;
    blockReduce2(s, ss);
    float mu = s * (1.0f / 1024.0f);
    float var = ss * (1.0f / 1024.0f) - mu * mu;
    float r = rsqrtf(var + 1e-5f);
    int d = threadIdx.x * 4;
    const float* mb = g_mod + b * MODW;
    float o0 = (v.x - mu) * r * w[d + 0] * (1.0f + mb[scOff + d + 0]) + mb[shOff + d + 0];
    float o1 = (v.y - mu) * r * w[d + 1] * (1.0f + mb[scOff + d + 1]) + mb[shOff + d + 1];
    float o2 = (v.z - mu) * r * w[d + 2] * (1.0f + mb[scOff + d + 2]) + mb[shOff + d + 2];
    float o3 = (v.w - mu) * r * w[d + 3] * (1.0f + mb[scOff + d + 3]) + mb[shOff + d + 3];
    ((uint2*)(out + (size_t)row * DMODEL))[threadIdx.x] =
        make_uint2(h2u(__floats2half2_rn(o0, o1)), h2u(__floats2half2_rn(o2, o3)));
}

// ---------------- 3) FP16 tensor-core GEMM, 128x128x32, ldmatrix ----------------
// MODE 0: Ch = acc (half)        MODE 1: Cf = res + gate * acc
// MODE 2: Ch = gelu(acc + bias)  MODE 3: Cf = res + gate * (acc + bias)
#define AH_STRIDE 40    // halfs; 80B = 5 units mod 8 -> conflict-free
#define BH_STRIDE 136   // halfs; 272B = 17 units = 1 mod 8 -> conflict-free

template<int MODE>
__global__ void __launch_bounds__(256, 2)
mma_gemm_h(const __half* __restrict__ A, const __half* __restrict__ B, void* __restrict__ Cp,
           int M, int N, int K,
           const float* __restrict__ res, const float* __restrict__ bias,
           const float* __restrict__ gate) {
    __shared__ __half As[2][128 * AH_STRIDE];
    __shared__ __half Bs[2][32 * BH_STRIDE];
    const int t = threadIdx.x;
    const int lane = t & 31, wid = t >> 5;
    const int warp_m = wid & 1, warp_n = wid >> 1;
    const int rowBase = blockIdx.y * 128, colBase = blockIdx.x * 128;
    const int nk = K >> 5;

    float acc[4][4][4];
    #pragma unroll
    for (int mt = 0; mt < 4; mt++)
        #pragma unroll
        for (int nt = 0; nt < 4; nt++)
            #pragma unroll
            for (int f = 0; f < 4; f++) acc[mt][nt][f] = 0.0f;

    auto load_stage = [&](int kt, int buf) {
        #pragma unroll
        for (int i = 0; i < 2; i++) {
            int idx = t + i * 256;           // 0..511: 128 rows x 4 chunks(8h)
            int r = idx >> 2, q = idx & 3;
            cpa16((uint32_t)__cvta_generic_to_shared(&As[buf][r * AH_STRIDE + q * 8]),
                  A + (size_t)(rowBase + r) * K + kt * 32 + q * 8);
        }
        #pragma unroll
        for (int i = 0; i < 2; i++) {
            int idx = t + i * 256;           // 0..511: 32 krows x 16 chunks
            int k = idx >> 4, cq = idx & 15;
            cpa16((uint32_t)__cvta_generic_to_shared(&Bs[buf][k * BH_STRIDE + cq * 8]),
                  B + (size_t)(kt * 32 + k) * N + colBase + cq * 8);
        }
        asm volatile("cp.async.commit_group;" ::: "memory");
    };

    load_stage(0, 0);
    for (int kt = 0; kt < nk; kt++) {
        if (kt + 1 < nk) {
            load_stage(kt + 1, (kt + 1) & 1);
            asm volatile("cp.async.wait_group 1;" ::: "memory");
        } else {
            asm volatile("cp.async.wait_group 0;" ::: "memory");
        }
        __syncthreads();
        const __half* as = As[kt & 1];
        const __half* bs = Bs[kt & 1];
        #pragma unroll
        for (int ks = 0; ks < 2; ks++) {
            uint32_t af[4][4], bw[2][4];
            #pragma unroll
            for (int mt = 0; mt < 4; mt++) {
                int row = warp_m * 64 + mt * 16 + (lane & 15);
                int col = ks * 16 + 8 * (lane >> 4);
                ldsm_x4(af[mt][0], af[mt][1], af[mt][2], af[mt][3],
                        (uint32_t)__cvta_generic_to_shared(&as[row * AH_STRIDE + col]));
            }
            #pragma unroll
            for (int np = 0; np < 2; np++) {
                int row = ks * 16 + (lane & 7) + 8 * ((lane >> 3) & 1);
                int col = warp_n * 32 + np * 16 + 8 * (lane >> 4);
                ldsm_x4_t(bw[np][0], bw[np][1], bw[np][2], bw[np][3],
                          (uint32_t)__cvta_generic_to_shared(&bs[row * BH_STRIDE + col]));
            }
            #pragma unroll
            for (int mt = 0; mt < 4; mt++)
                #pragma unroll
                for (int nt = 0; nt < 4; nt++)
                    mma_f16(acc[mt][nt], af[mt], &bw[nt >> 1][(nt & 1) * 2]);
        }
        __syncthreads();
    }

    #pragma unroll
    for (int mt = 0; mt < 4; mt++) {
        #pragma unroll
        for (int nt = 0; nt < 4; nt++) {
            #pragma unroll
            for (int half_ = 0; half_ < 2; half_++) {
                int gr = rowBase + warp_m * 64 + mt * 16 + (lane >> 2) + half_ * 8;
                int gc = colBase + warp_n * 32 + nt * 8 + (lane & 3) * 2;
                int bb = gr >> 11;
                size_t off = (size_t)gr * N + gc;
                float v0 = acc[mt][nt][half_ * 2 + 0];
                float v1 = acc[mt][nt][half_ * 2 + 1];
                if (MODE == 0) {
                    *(__half2*)((__half*)Cp + off) = __floats2half2_rn(v0, v1);
                } else if (MODE == 1) {
                    float* Cf = (float*)Cp;
                    Cf[off]     = res[off]     + gate[bb * MODW + gc]     * v0;
                    Cf[off + 1] = res[off + 1] + gate[bb * MODW + gc + 1] * v1;
                } else if (MODE == 2) {
                    *(__half2*)((__half*)Cp + off) =
                        __floats2half2_rn(gelu_tanh(v0 + bias[gc]), gelu_tanh(v1 + bias[gc + 1]));
                } else {
                    float* Cf = (float*)Cp;
                    Cf[off]     = res[off]     + gate[bb * MODW + gc]     * (v0 + bias[gc]);
                    Cf[off + 1] = res[off + 1] + gate[bb * MODW + gc + 1] * (v1 + bias[gc + 1]);
                }
            }
        }
    }
}

// ---------------- 4) rmsnorm + rope on q,k (half in/out); q pre-scaled ----------------
__global__ void __launch_bounds__(1024)
rope_kernel(const float* __restrict__ qw, const float* __restrict__ kw,
            const float* __restrict__ cosb, const float* __restrict__ sinb) {
    __shared__ float sm[1024];
    __shared__ float part[32];
    int row = blockIdx.x;
    int s = row & (SEQ - 1);
    int t = threadIdx.x;
    int h = t >> 6, hd = t & 63;
    int wrp = t >> 5, lane = t & 31;
    float cs = cosb[s * HDIM + hd], sn = sinb[s * HDIM + hd];
    const float lscale = 0.125f * 1.4426950408889634f;
    #pragma unroll
    for (int which = 0; which < 2; which++) {
        size_t base = ((size_t)row * 3 + which) * DMODEL;
        float v = __half2float(g_qkvh[base + t]);
        float ss = v * v;
        #pragma unroll
        for (int off = 16; off; off >>= 1) ss += __shfl_xor_sync(0xffffffffu, ss, off);
        if (lane == 0) part[wrp] = ss;
        __syncthreads();
        float sumsq = part[2 * h] + part[2 * h + 1];
        float r = rsqrtf(sumsq * (1.0f / 64.0f) + 1e-6f);
        const float* ww = which ? kw : qw;
        float xn = v * r * ww[hd];
        sm[t] = xn;
        __syncthreads();
        float partner = sm[h * 64 + ((hd + 32) & 63)];
        float rot = (hd < 32) ? -partner : partner;
        float val = xn * cs + rot * sn;
        if (which == 0) val *= lscale;
        g_qkvh[base + t] = __float2half_rn(val);
        __syncthreads();
    }
}

// ---------------- 5) flash attention, fp16 tensor cores, P in registers ----------------
#define KVS 72   // halfs; 144B = 9 units = 1 mod 8 -> conflict-free ldmatrix
#define ATTN_SMEM (2 * 2 * 64 * KVS * 2)   // 2 bufs x (K+V) x 64 x KVS halfs

__global__ void __launch_bounds__(128)
attn_kernel() {
    extern __shared__ __half smemh[];
    __half* ksm = smemh;                 // [2][64*KVS]
    __half* vsm = smemh + 2 * 64 * KVS;  // [2][64*KVS]

    const int qt = blockIdx.x, h = blockIdx.y, b = blockIdx.z;
    const int t = threadIdx.x;
    const int lane = t & 31, w = t >> 5;
    const int r0 = lane >> 2, q4 = lane & 3;

    const size_t kbase = ((size_t)(b * SEQ) * 3 + 1) * DMODEL + h * HDIM;
    const size_t vbase = kbase + DMODEL;
    const int qrow0 = b * SEQ + qt * 64 + w * 16;
    const __half* Qh = g_qkvh + (size_t)qrow0 * 3 * DMODEL + h * HDIM;

    // Q A-fragments: 4 k16-steps (scaled+rounded by rope)
    uint32_t qf[4][4];
    #pragma unroll
    for (int s = 0; s < 4; s++) {
        int kk = 16 * s + 2 * q4;
        qf[s][0] = *(const uint32_t*)(Qh + (size_t)(r0    ) * 3072 + kk    );
        qf[s][1] = *(const uint32_t*)(Qh + (size_t)(r0 + 8) * 3072 + kk    );
        qf[s][2] = *(const uint32_t*)(Qh + (size_t)(r0    ) * 3072 + kk + 8);
        qf[s][3] = *(const uint32_t*)(Qh + (size_t)(r0 + 8) * 3072 + kk + 8);
    }

    float of[8][4];
    #pragma unroll
    for (int j = 0; j < 8; j++)
        #pragma unroll
        for (int f = 0; f < 4; f++) of[j][f] = 0.0f;
    float m0 = -1e30f, m1 = -1e30f, l0 = 0.0f, l1 = 0.0f;

    auto loadKV = [&](int k0, int buf) {
        #pragma unroll
        for (int i = 0; i < 4; i++) {
            int idx = t + i * 128;           // 0..511: 64 rows x 8 chunks(8h)
            int row = idx >> 3, c = idx & 7;
            cpa16((uint32_t)__cvta_generic_to_shared(&ksm[buf * 64 * KVS + row * KVS + c * 8]),
                  g_qkvh + kbase + (size_t)(k0 + row) * 3072 + c * 8);
            cpa16((uint32_t)__cvta_generic_to_shared(&vsm[buf * 64 * KVS + row * KVS + c * 8]),
                  g_qkvh + vbase + (size_t)(k0 + row) * 3072 + c * 8);
        }
        asm volatile("cp.async.commit_group;" ::: "memory");
    };

    loadKV(0, 0);
    for (int kt = 0; kt < SEQ / 64; kt++) {
        if (kt + 1 < SEQ / 64) {
            loadKV((kt + 1) * 64, (kt + 1) & 1);
            asm volatile("cp.async.wait_group 1;" ::: "memory");
        } else {
            asm volatile("cp.async.wait_group 0;" ::: "memory");
        }
        __syncthreads();
        const __half* kb = ksm + (kt & 1) * 64 * KVS;
        const __half* vb = vsm + (kt & 1) * 64 * KVS;

        // S = Q K^T : ldmatrix.x4 on K[key][d] gives B-frags for 2 n-tiles per call
        float sf[8][4];
        #pragma unroll
        for (int j = 0; j < 8; j++)
            #pragma unroll
            for (int f = 0; f < 4; f++) sf[j][f] = 0.0f;
        #pragma unroll
        for (int s = 0; s < 4; s++) {
            #pragma unroll
            for (int np = 0; np < 4; np++) {
                uint32_t bw[4];
                int row = 16 * np + (lane & 7) + 8 * (lane >> 4);          // key
                int col = 16 * s + 8 * ((lane >> 3) & 1);                  // d
                ldsm_x4(bw[0], bw[1], bw[2], bw[3],
                        (uint32_t)__cvta_generic_to_shared(&kb[row * KVS + col]));
                mma_f16(sf[2 * np],     qf[s], &bw[0]);
                mma_f16(sf[2 * np + 1], qf[s], &bw[2]);
            }
        }

        // online softmax on fragment layout
        float mx0 = -1e30f, mx1 = -1e30f;
        #pragma unroll
        for (int j = 0; j < 8; j++) {
            mx0 = fmaxf(mx0, fmaxf(sf[j][0], sf[j][1]));
            mx1 = fmaxf(mx1, fmaxf(sf[j][2], sf[j][3]));
        }
        #pragma unroll
        for (int off = 1; off < 4; off <<= 1) {
            mx0 = fmaxf(mx0, __shfl_xor_sync(0xffffffffu, mx0, off));
            mx1 = fmaxf(mx1, __shfl_xor_sync(0xffffffffu, mx1, off));
        }
        float nm0 = fmaxf(m0, mx0), nm1 = fmaxf(m1, mx1);
        float a0 = ex2(m0 - nm0), a1 = ex2(m1 - nm1);
        float s0 = 0.0f, s1 = 0.0f;
        #pragma unroll
        for (int j = 0; j < 8; j++) {
            sf[j][0] = ex2(sf[j][0] - nm0);
            sf[j][1] = ex2(sf[j][1] - nm0);
            sf[j][2] = ex2(sf[j][2] - nm1);
            sf[j][3] = ex2(sf[j][3] - nm1);
            s0 += sf[j][0] + sf[j][1];
            s1 += sf[j][2] + sf[j][3];
        }
        #pragma unroll
        for (int off = 1; off < 4; off <<= 1) {
            s0 += __shfl_xor_sync(0xffffffffu, s0, off);
            s1 += __shfl_xor_sync(0xffffffffu, s1, off);
        }
        m0 = nm0; m1 = nm1;
        l0 = l0 * a0 + s0;
        l1 = l1 * a1 + s1;
        #pragma unroll
        for (int j = 0; j < 8; j++) {
            of[j][0] *= a0; of[j][1] *= a0;
            of[j][2] *= a1; of[j][3] *= a1;
        }

        // O += P V : P converted to A-frags in registers (no smem roundtrip)
        #pragma unroll
        for (int s = 0; s < 4; s++) {
            uint32_t pf[4];
            pf[0] = h2u(__floats2half2_rn(sf[2 * s][0],     sf[2 * s][1]));
            pf[1] = h2u(__floats2half2_rn(sf[2 * s][2],     sf[2 * s][3]));
            pf[2] = h2u(__floats2half2_rn(sf[2 * s + 1][0], sf[2 * s + 1][1]));
            pf[3] = h2u(__floats2half2_rn(sf[2 * s + 1][2], sf[2 * s + 1][3]));
            #pragma unroll
            for (int np = 0; np < 4; np++) {
                uint32_t bw[4];
                int row = 16 * s + (lane & 7) + 8 * ((lane >> 3) & 1);     // key
                int col = 16 * np + 8 * (lane >> 4);                       // d
                ldsm_x4_t(bw[0], bw[1], bw[2], bw[3],
                          (uint32_t)__cvta_generic_to_shared(&vb[row * KVS + col]));
                mma_f16(of[2 * np],     pf, &bw[0]);
                mma_f16(of[2 * np + 1], pf, &bw[2]);
            }
        }
        __syncthreads();
    }

    float inv0 = 1.0f / l0, inv1 = 1.0f / l1;
    #pragma unroll
    for (int j = 0; j < 8; j++) {
        size_t base0 = (size_t)(qrow0 + r0    ) * DMODEL + h * HDIM + 8 * j + 2 * q4;
        size_t base1 = (size_t)(qrow0 + r0 + 8) * DMODEL + h * HDIM + 8 * j + 2 * q4;
        *(__half2*)&g_attnh[base0] = __floats2half2_rn(of[j][0] * inv0, of[j][1] * inv0);
        *(__half2*)&g_attnh[base1] = __floats2half2_rn(of[j][2] * inv1, of[j][3] * inv1);
    }
}

// ---------------- launch ----------------
extern "C" void kernel_launch(void* const* d_in, const int* in_sizes, int n_in,
                              void* d_out, int out_size) {
    const float* x       = (const float*)d_in[0];
    const float* cosb    = (const float*)d_in[1];
    const float* sinb    = (const float*)d_in[2];
    const float* c       = (const float*)d_in[3];
    const float* norm1_w = (const float*)d_in[4];
    const float* Wqkv    = (const float*)d_in[5];
    const float* Wout    = (const float*)d_in[6];
    const float* q_norm_w = (const float*)d_in[7];
    const float* k_norm_w = (const float*)d_in[8];
    const float* norm2_w = (const float*)d_in[9];
    const float* W1      = (const float*)d_in[10];
    const float* b1      = (const float*)d_in[11];
    const float* W2      = (const float*)d_in[12];
    const float* b2      = (const float*)d_in[13];
    const float* ada_W   = (const float*)d_in[14];
    const float* ada_b   = (const float*)d_in[15];
    float* out = (float*)d_out;

    float *p_x2;
    __half *p_xnh, *p_qkvh, *p_attnh, *p_hh, *p_wqkvh, *p_wouth, *p_w1h, *p_w2h;
    float *p_mod;
    cudaGetSymbolAddress((void**)&p_mod, g_mod);
    cudaGetSymbolAddress((void**)&p_x2, g_x2);
    cudaGetSymbolAddress((void**)&p_xnh, g_xnh);
    cudaGetSymbolAddress((void**)&p_qkvh, g_qkvh);
    cudaGetSymbolAddress((void**)&p_attnh, g_attnh);
    cudaGetSymbolAddress((void**)&p_hh, g_hh);
    cudaGetSymbolAddress((void**)&p_wqkvh, g_wqkvh);
    cudaGetSymbolAddress((void**)&p_wouth, g_wouth);
    cudaGetSymbolAddress((void**)&p_w1h, g_w1h);
    cudaGetSymbolAddress((void**)&p_w2h, g_w2h);

    cudaFuncSetAttribute(attn_kernel, cudaFuncAttributeMaxDynamicSharedMemorySize, ATTN_SMEM);

    // 0) weights -> half
    cvth_kernel<<<(3 * DMODEL * DMODEL) / 1024, 256>>>(Wqkv, p_wqkvh);
    cvth_kernel<<<(DMODEL * DMODEL) / 1024, 256>>>(Wout, p_wouth);
    cvth_kernel<<<(DMODEL * DFF) / 1024, 256>>>(W1, p_w1h);
    cvth_kernel<<<(DFF * DMODEL) / 1024, 256>>>(W2, p_w2h);
    // 1) adaLN modulation vectors
    mod_kernel<<<dim3(MODW / 256, BATCH), 256>>>(c, ada_W, ada_b);
    // 2) LN1 + modulate -> half
    ln_mod_kernel<<<NROWS, 256>>>(x, norm1_w, 0, 1024, p_xnh);
    // 3) qkv = xn @ Wqkv -> half
    mma_gemm_h<0><<<dim3(3 * DMODEL / 128, NROWS / 128), 256>>>(
        p_xnh, p_wqkvh, p_qkvh, NROWS, 3 * DMODEL, DMODEL, nullptr, nullptr, nullptr);
    // 4) rmsnorm + rope (q pre-scaled)
    rope_kernel<<<NROWS, 1024>>>(q_norm_w, k_norm_w, cosb, sinb);
    // 5) attention -> half
    attn_kernel<<<dim3(SEQ / 64, NHEADS, BATCH), 128, ATTN_SMEM>>>();
    // 6) x2 = x + g_msa * (attn @ Wout)   (fp32 out)
    mma_gemm_h<1><<<dim3(DMODEL / 128, NROWS / 128), 256>>>(
        p_attnh, p_wouth, p_x2, NROWS, DMODEL, DMODEL, x, nullptr, p_mod + 2 * 1024);
    // 7) LN2 + modulate -> half
    ln_mod_kernel<<<NROWS, 256>>>(p_x2, norm2_w, 3 * 1024, 4 * 1024, p_xnh);
    // 8) h = gelu(xn @ W1 + b1) -> half
    mma_gemm_h<2><<<dim3(DFF / 128, NROWS / 128), 256>>>(
        p_xnh, p_w1h, p_hh, NROWS, DFF, DMODEL, nullptr, b1, nullptr);
    // 9) out = x2 + g_mlp * (h @ W2 + b2)  (fp32 out)
    mma_gemm_h<3><<<dim3(DMODEL / 128, NROWS / 128), 256>>>(
        p_hh, p_w2h, out, NROWS, DMODEL, DFF, p_x2, b2, p_mod + 5 * 1024);
}